// round 14
// baseline (speedup 1.0000x reference)
#include <cuda_runtime.h>
#include <cuda_bf16.h>
#include <math.h>
#include <stdint.h>

#define NN 50000
#define EE 800000
#define GI 64
#define HCDIM 256

// ---------------- scratch (static device globals; no allocation) ----------------
__device__ __nv_bfloat16 g_hb[(size_t)NN * HCDIM];   // GEMM output h (bf16, gathered)
__device__ __nv_bfloat16 g_ahi[(size_t)NN * HCDIM];  // A operand hi
__device__ __nv_bfloat16 g_alo[(size_t)NN * HCDIM];  // A operand lo
__device__ __nv_bfloat16 g_wt0hi[256 * 128], g_wt0lo[256 * 128];
__device__ __nv_bfloat16 g_wt1hi[256 * 256], g_wt1lo[256 * 256];
__device__ __nv_bfloat16 g_wtphi[128 * 256], g_wtplo[128 * 256];
__device__ float g_als[NN * 4];
__device__ float g_ald[NN * 4];
__device__ float g_gate[NN];
__device__ float g_pool[GI * HCDIM];
__device__ float g_gm[GI];
__device__ float g_ginv[GI];
__device__ int   g_cnt[NN];
__device__ int   g_off[NN + 1];
__device__ int   g_fill[NN];
__device__ int   g_srcv[EE + NN];
__device__ int   g_gstart[GI + 1];
__device__ int   g_bsum[64];

// ---------------- helpers ----------------
__device__ __forceinline__ void mma_bf16(float* c, const uint32_t* a, const uint32_t* b) {
    asm volatile(
        "mma.sync.aligned.m16n8k16.row.col.f32.bf16.bf16.f32 "
        "{%0,%1,%2,%3}, {%4,%5,%6,%7}, {%8,%9}, {%0,%1,%2,%3};"
        : "+f"(c[0]), "+f"(c[1]), "+f"(c[2]), "+f"(c[3])
        : "r"(a[0]), "r"(a[1]), "r"(a[2]), "r"(a[3]), "r"(b[0]), "r"(b[1]));
}
#define LDM4(r, addr) \
    asm volatile("ldmatrix.sync.aligned.m8n8.x4.shared.b16 {%0,%1,%2,%3}, [%4];" \
        : "=r"((r)[0]), "=r"((r)[1]), "=r"((r)[2]), "=r"((r)[3]) : "r"(addr))
__device__ __forceinline__ uint32_t smem_u32(const void* p) {
    uint32_t a;
    asm("{ .reg .u64 t; cvta.to.shared.u64 t, %1; cvt.u32.u64 %0, t; }" : "=r"(a) : "l"(p));
    return a;
}
__device__ __forceinline__ void cpa16(uint32_t dst, const void* src, uint32_t sz) {
    asm volatile("cp.async.cg.shared.global [%0], [%1], 16, %2;"
                 :: "r"(dst), "l"(src), "r"(sz));
}
#define CP_COMMIT() asm volatile("cp.async.commit_group;")
#define CP_WAIT(n)  asm volatile("cp.async.wait_group %0;" :: "n"(n))
__device__ __forceinline__ uint32_t packbf(float a, float b) {
    return (uint32_t)__bfloat16_as_ushort(__float2bfloat16(a)) |
           ((uint32_t)__bfloat16_as_ushort(__float2bfloat16(b)) << 16);
}
// L1-bypass loads (random gathers -> keep out of L1)
__device__ __forceinline__ uint4 ldcg16(const void* p) {
    uint4 v;
    asm volatile("ld.global.cg.v4.u32 {%0,%1,%2,%3}, [%4];"
                 : "=r"(v.x), "=r"(v.y), "=r"(v.z), "=r"(v.w) : "l"(p));
    return v;
}
__device__ __forceinline__ float ldcgf(const float* p) {
    float v;
    asm volatile("ld.global.cg.f32 %0, [%1];" : "=f"(v) : "l"(p));
    return v;
}

// ---------------- fused prep: split x + edge count + all weight splits ----------
__global__ void prep_k(const float* __restrict__ x, __nv_bfloat16* xhi, __nv_bfloat16* xlo,
                       int nx, const int* __restrict__ ei, int E, int* cnt,
                       const float* __restrict__ W0, __nv_bfloat16* w0h, __nv_bfloat16* w0l,
                       const float* __restrict__ W1, __nv_bfloat16* w1h, __nv_bfloat16* w1l,
                       const float* __restrict__ pW1, __nv_bfloat16* wph, __nv_bfloat16* wpl) {
    int i = blockIdx.x * blockDim.x + threadIdx.x;
    if (i < nx) {
        float v = x[i];
        __nv_bfloat16 h = __float2bfloat16(v);
        xhi[i] = h;
        xlo[i] = __float2bfloat16(v - __bfloat162float(h));
    }
    if (i < E) atomicAdd(&cnt[ei[E + i]], 1);
    if (i < 128 * 256) {
        int k = i >> 8, n = i & 255;
        float v = W0[i];
        __nv_bfloat16 h = __float2bfloat16(v);
        w0h[n * 128 + k] = h;
        w0l[n * 128 + k] = __float2bfloat16(v - __bfloat162float(h));
    }
    if (i < 256 * 256) {
        int k = i >> 8, n = i & 255;
        float v = W1[i];
        __nv_bfloat16 h = __float2bfloat16(v);
        w1h[n * 256 + k] = h;
        w1l[n * 256 + k] = __float2bfloat16(v - __bfloat162float(h));
    }
    if (i < 256 * 128) {
        int k = i >> 7, n = i & 127;
        float v = pW1[i];
        __nv_bfloat16 h = __float2bfloat16(v);
        wph[n * 256 + k] = h;
        wpl[n * 256 + k] = __float2bfloat16(v - __bfloat162float(h));
    }
}

// ---------------- CSR scan (+fused gstart) ----------------
__global__ void scan_block_k(const int* __restrict__ cnt, int* __restrict__ off,
                             int* __restrict__ bsum, int n,
                             const int* __restrict__ batch, int* __restrict__ gstart, int G) {
    int i = blockIdx.x * 1024 + threadIdx.x;
    int lane = threadIdx.x & 31, wid = threadIdx.x >> 5;
    int v = (i < n) ? cnt[i] + 1 : 0;   // +1 = self loop
    int s = v;
#pragma unroll
    for (int d = 1; d < 32; d <<= 1) {
        int t = __shfl_up_sync(0xffffffffu, s, d);
        if (lane >= d) s += t;
    }
    __shared__ int wsum[32];
    if (lane == 31) wsum[wid] = s;
    __syncthreads();
    if (wid == 0) {
        int w = wsum[lane];
#pragma unroll
        for (int d = 1; d < 32; d <<= 1) {
            int t = __shfl_up_sync(0xffffffffu, w, d);
            if (lane >= d) w += t;
        }
        wsum[lane] = w;
    }
    __syncthreads();
    int base = wid ? wsum[wid - 1] : 0;
    if (i < n) off[i] = base + s - v;
    if (threadIdx.x == 1023) bsum[blockIdx.x] = base + s;
    if (i < n) {
        int b = batch[i];
        if (i == 0) { for (int g = 0; g <= b; g++) gstart[g] = 0; }
        else {
            int pb = batch[i - 1];
            if (pb != b) for (int g = pb + 1; g <= b; g++) gstart[g] = i;
        }
        if (i == n - 1) for (int g = b + 1; g <= G; g++) gstart[g] = n;
    }
}
__global__ void scan_add_fill_k(const int* __restrict__ bsum, int* __restrict__ off,
                                int* __restrict__ fill, int* __restrict__ srcv,
                                int n, int nb) {
    __shared__ int sh[64];
    int t = threadIdx.x;   // 256
    if (t < 64) sh[t] = (t < nb) ? bsum[t] : 0;
    __syncthreads();
#pragma unroll
    for (int d = 1; d < 64; d <<= 1) {
        int x = (t >= d && t < 64) ? sh[t - d] : 0;
        __syncthreads();
        if (t < 64) sh[t] += x;
        __syncthreads();
    }
    int i = blockIdx.x * 256 + t;
    if (i < n) {
        int b = i >> 10;
        int o = off[i] + (b ? sh[b - 1] : 0);
        off[i] = o;
        fill[i] = o + 1;
        srcv[o] = i;
    }
    if (blockIdx.x == 0 && t == 0) off[n] = sh[nb - 1];
}
__global__ void scatter_k(const int* __restrict__ ei, int E, int* fill, int* srcv) {
    int e = blockIdx.x * blockDim.x + threadIdx.x;
    if (e < E) {
        int s = ei[e];
        int d = ei[E + e];
        int p = atomicAdd(&fill[d], 1);
        srcv[p] = s;
    }
}

// ---------------- HMMA GEMM with cp.async double buffering --------------------
#define GSTG 40960
#define OFF_AH 0
#define OFF_AL 10240
#define OFF_BH 20480
#define OFF_BL 30720
template <bool GATE>
__global__ __launch_bounds__(256, 2)
void gemm_mma_k(const __nv_bfloat16* __restrict__ ahi, const __nv_bfloat16* __restrict__ alo,
                const __nv_bfloat16* __restrict__ bhi, const __nv_bfloat16* __restrict__ blo,
                __nv_bfloat16* __restrict__ Cb, float* __restrict__ als, float* __restrict__ ald,
                const float* __restrict__ asrc, const float* __restrict__ adst,
                const float* __restrict__ pb1, const float* __restrict__ pW2,
                const float* __restrict__ pb2, float* __restrict__ gate,
                int M, int K, int NTT) {
    extern __shared__ char dynsm[];
    __shared__ float sgate[128];
    uint32_t sbase = smem_u32(dynsm);

    int tid = threadIdx.x;
    int wid = tid >> 5, lane = tid & 31;
    int wr = wid >> 1, wc = wid & 1;
    int row0 = blockIdx.x * 128;
    int nbase = blockIdx.y * 128;

    float acc[2][8][4];
#pragma unroll
    for (int mt = 0; mt < 2; mt++)
#pragma unroll
        for (int nt = 0; nt < 8; nt++)
#pragma unroll
            for (int q = 0; q < 4; q++) acc[mt][nt][q] = 0.f;

    int r4 = lane >> 2, k2 = (lane & 3) * 2;
    uint32_t aoffB = (uint32_t)(((wr * 32 + (lane & 15)) * 40 + (lane >> 4) * 8) * 2);
    uint32_t boffB = (uint32_t)(((wc * 64 + ((lane >> 4) & 1) * 8 + (lane & 7)) * 40 +
                                 ((lane >> 3) & 1) * 8) * 2);

    int ntiles = K >> 5;
    auto issue = [&](int kt) {
        uint32_t sb2 = sbase + (uint32_t)(kt & 1) * GSTG;
        int kbase = kt << 5;
#pragma unroll
        for (int i = 0; i < 2; i++) {
            int idx = tid + i * 256;
            int r = idx >> 2, q = idx & 3;
            int row = row0 + r;
            uint32_t doff = (uint32_t)((r * 40 + q * 8) * 2);
            size_t ga = (size_t)row * K + kbase + q * 8;
            uint32_t sz = (row < M) ? 16u : 0u;
            cpa16(sb2 + OFF_AH + doff, ahi + ga, sz);
            cpa16(sb2 + OFF_AL + doff, alo + ga, sz);
            size_t gb = (size_t)(nbase + r) * K + kbase + q * 8;
            cpa16(sb2 + OFF_BH + doff, bhi + gb, 16u);
            cpa16(sb2 + OFF_BL + doff, blo + gb, 16u);
        }
        CP_COMMIT();
    };

    issue(0);
    for (int kt = 0; kt < ntiles; kt++) {
        if (kt + 1 < ntiles) { issue(kt + 1); CP_WAIT(1); }
        else                 { CP_WAIT(0); }
        __syncthreads();
        uint32_t sb2 = sbase + (uint32_t)(kt & 1) * GSTG;
#pragma unroll
        for (int kk = 0; kk < 32; kk += 16) {
            uint32_t a_h[2][4], a_l[2][4];
            uint32_t ab = aoffB + kk * 2;
            LDM4(a_h[0], sb2 + OFF_AH + ab);
            LDM4(a_l[0], sb2 + OFF_AL + ab);
            LDM4(a_h[1], sb2 + OFF_AH + ab + 16 * 80);
            LDM4(a_l[1], sb2 + OFF_AL + ab + 16 * 80);
#pragma unroll
            for (int nh = 0; nh < 2; nh++) {
                uint32_t b_h[4][2], b_l[4][2];
                uint32_t bb = boffB + (nh * 32 * 40 + kk) * 2;
                uint32_t t0[4], t1[4];
                LDM4(t0, sb2 + OFF_BH + bb);
                LDM4(t1, sb2 + OFF_BH + bb + 16 * 80);
                b_h[0][0] = t0[0]; b_h[0][1] = t0[1]; b_h[1][0] = t0[2]; b_h[1][1] = t0[3];
                b_h[2][0] = t1[0]; b_h[2][1] = t1[1]; b_h[3][0] = t1[2]; b_h[3][1] = t1[3];
                LDM4(t0, sb2 + OFF_BL + bb);
                LDM4(t1, sb2 + OFF_BL + bb + 16 * 80);
                b_l[0][0] = t0[0]; b_l[0][1] = t0[1]; b_l[1][0] = t0[2]; b_l[1][1] = t0[3];
                b_l[2][0] = t1[0]; b_l[2][1] = t1[1]; b_l[3][0] = t1[2]; b_l[3][1] = t1[3];
#pragma unroll
                for (int mt = 0; mt < 2; mt++)
#pragma unroll
                    for (int j = 0; j < 4; j++) {
                        float* cc = acc[mt][nh * 4 + j];
                        mma_bf16(cc, a_h[mt], b_h[j]);
                        mma_bf16(cc, a_h[mt], b_l[j]);
                        mma_bf16(cc, a_l[mt], b_h[j]);
                    }
            }
        }
        __syncthreads();
    }

    if constexpr (!GATE) {
        int hd = blockIdx.y * 2 + wc;
#pragma unroll
        for (int mt = 0; mt < 2; mt++) {
#pragma unroll
            for (int half = 0; half < 2; half++) {
                int row = row0 + wr * 32 + mt * 16 + r4 + half * 8;
                float ps = 0.f, pd = 0.f;
#pragma unroll
                for (int nt = 0; nt < 8; nt++) {
                    float c0 = acc[mt][nt][half * 2 + 0];
                    float c1 = acc[mt][nt][half * 2 + 1];
                    int gc = nbase + wc * 64 + nt * 8 + k2;
                    if (row < M)
                        *(uint32_t*)(Cb + (size_t)row * NTT + gc) = packbf(c0, c1);
                    ps += c0 * asrc[gc] + c1 * asrc[gc + 1];
                    pd += c0 * adst[gc] + c1 * adst[gc + 1];
                }
                ps += __shfl_xor_sync(0xffffffffu, ps, 1);
                ps += __shfl_xor_sync(0xffffffffu, ps, 2);
                pd += __shfl_xor_sync(0xffffffffu, pd, 1);
                pd += __shfl_xor_sync(0xffffffffu, pd, 2);
                if (row < M && (lane & 3) == 0) {
                    als[row * 4 + hd] = ps;
                    ald[row * 4 + hd] = pd;
                }
            }
        }
    } else {
        if (tid < 128) sgate[tid] = 0.f;
        __syncthreads();
#pragma unroll
        for (int mt = 0; mt < 2; mt++) {
#pragma unroll
            for (int half = 0; half < 2; half++) {
                int rl = wr * 32 + mt * 16 + r4 + half * 8;
                float p = 0.f;
#pragma unroll
                for (int nt = 0; nt < 8; nt++) {
                    float c0 = acc[mt][nt][half * 2 + 0];
                    float c1 = acc[mt][nt][half * 2 + 1];
                    int gc = wc * 64 + nt * 8 + k2;
                    p += fmaxf(c0 + pb1[gc], 0.f) * pW2[gc];
                    p += fmaxf(c1 + pb1[gc + 1], 0.f) * pW2[gc + 1];
                }
                p += __shfl_xor_sync(0xffffffffu, p, 1);
                p += __shfl_xor_sync(0xffffffffu, p, 2);
                if ((lane & 3) == 0) atomicAdd(&sgate[rl], p);
            }
        }
        __syncthreads();
        if (tid < 128) {
            int row = row0 + tid;
            if (row < M) gate[row] = sgate[tid] + pb2[0];
        }
    }
}

// ---------------- fused edge softmax + aggregate + bias + LN + ReLU ------------
// Round-9 loop structure; random gathers use ld.global.cg (L1 bypass).
__device__ __forceinline__ float lrelu(float x) { return x > 0.f ? x : 0.2f * x; }

__global__ void edge_agg_k(const int* __restrict__ off, const int* __restrict__ csr,
                           const __nv_bfloat16* __restrict__ hb, const float* __restrict__ als,
                           const float* __restrict__ ald, const float* __restrict__ bias,
                           const float* __restrict__ gamma, const float* __restrict__ beta,
                           __nv_bfloat16* __restrict__ ohi, __nv_bfloat16* __restrict__ olo,
                           int n) {
    int node = (blockIdx.x * blockDim.x + threadIdx.x) >> 5;
    int lane = threadIdx.x & 31;
    if (node >= n) return;
    int beg = off[node], end = off[node + 1];

    int hd = lane >> 3;
    int eoff = lane & 7;
    float adh = ald[node * 4 + hd];

    float sexp = 0.f;
    float4 a0 = make_float4(0.f, 0.f, 0.f, 0.f);
    float4 a1 = make_float4(0.f, 0.f, 0.f, 0.f);
    for (int cb = beg; cb < end; cb += 8) {
        int cnt = min(8, end - cb);
        float ev = 0.f;
        int smine = 0;
        if (eoff < cnt) {
            smine = csr[cb + eoff];
            ev = __expf(lrelu(ldcgf(als + (size_t)smine * 4 + hd) + adh));
        }
        sexp += ev;
        int lbase = lane & 24;
        for (int e = 0; e < cnt; e++) {
            float w = __shfl_sync(0xffffffffu, ev, lbase + e);
            int se = __shfl_sync(0xffffffffu, smine, e);
            uint4 u = ldcg16(hb + (size_t)se * 256 + lane * 8);
            float2 f0 = __bfloat1622float2(*(__nv_bfloat162*)&u.x);
            float2 f1 = __bfloat1622float2(*(__nv_bfloat162*)&u.y);
            float2 f2 = __bfloat1622float2(*(__nv_bfloat162*)&u.z);
            float2 f3 = __bfloat1622float2(*(__nv_bfloat162*)&u.w);
            a0.x += w * f0.x; a0.y += w * f0.y; a0.z += w * f1.x; a0.w += w * f1.y;
            a1.x += w * f2.x; a1.y += w * f2.y; a1.z += w * f3.x; a1.w += w * f3.y;
        }
    }
    sexp += __shfl_xor_sync(0xffffffffu, sexp, 1);
    sexp += __shfl_xor_sync(0xffffffffu, sexp, 2);
    sexp += __shfl_xor_sync(0xffffffffu, sexp, 4);
    float inv = 1.f / (sexp + 1e-16f);

    const float4* bp = (const float4*)(bias + lane * 8);
    float4 b0 = bp[0], b1 = bp[1];
    float y[8] = { a0.x * inv + b0.x, a0.y * inv + b0.y, a0.z * inv + b0.z, a0.w * inv + b0.w,
                   a1.x * inv + b1.x, a1.y * inv + b1.y, a1.z * inv + b1.z, a1.w * inv + b1.w };
    float ls = 0.f, lq = 0.f;
#pragma unroll
    for (int i = 0; i < 8; i++) { ls += y[i]; lq += y[i] * y[i]; }
#pragma unroll
    for (int o = 16; o > 0; o >>= 1) {
        ls += __shfl_xor_sync(0xffffffffu, ls, o);
        lq += __shfl_xor_sync(0xffffffffu, lq, o);
    }
    float mu  = ls * (1.f / 256.f);
    float var = lq * (1.f / 256.f) - mu * mu;
    float rs  = rsqrtf(var + 1e-5f);
    const float4* gp = (const float4*)(gamma + lane * 8);
    const float4* ep = (const float4*)(beta + lane * 8);
    float4 g0 = gp[0], g1 = gp[1], e0 = ep[0], e1 = ep[1];
    float o8[8];
    o8[0] = fmaxf((y[0] - mu) * rs * g0.x + e0.x, 0.f);
    o8[1] = fmaxf((y[1] - mu) * rs * g0.y + e0.y, 0.f);
    o8[2] = fmaxf((y[2] - mu) * rs * g0.z + e0.z, 0.f);
    o8[3] = fmaxf((y[3] - mu) * rs * g0.w + e0.w, 0.f);
    o8[4] = fmaxf((y[4] - mu) * rs * g1.x + e1.x, 0.f);
    o8[5] = fmaxf((y[5] - mu) * rs * g1.y + e1.y, 0.f);
    o8[6] = fmaxf((y[6] - mu) * rs * g1.z + e1.z, 0.f);
    o8[7] = fmaxf((y[7] - mu) * rs * g1.w + e1.w, 0.f);

    uint4 uh, ul;
    float r8[8];
#pragma unroll
    for (int i = 0; i < 8; i++) {
        __nv_bfloat16 hbv = __float2bfloat16(o8[i]);
        r8[i] = o8[i] - __bfloat162float(hbv);
    }
    uh.x = packbf(o8[0], o8[1]); uh.y = packbf(o8[2], o8[3]);
    uh.z = packbf(o8[4], o8[5]); uh.w = packbf(o8[6], o8[7]);
    ul.x = packbf(r8[0], r8[1]); ul.y = packbf(r8[2], r8[3]);
    ul.z = packbf(r8[4], r8[5]); ul.w = packbf(r8[6], r8[7]);
    ((uint4*)ohi)[(size_t)node * 32 + lane] = uh;
    ((uint4*)olo)[(size_t)node * 32 + lane] = ul;
}

// ---------------- pooling: stats -> parallel accumulate -> classifier ----------
__global__ void pool_stats_k(const float* __restrict__ gate, const int* __restrict__ gstart,
                             float* __restrict__ gm, float* __restrict__ ginv,
                             float* __restrict__ pool) {
    int g = blockIdx.x;
    int t = threadIdx.x;
    int gs = gstart[g], ge = gstart[g + 1];
    __shared__ float red[256];
    float lm = -1e30f;
    for (int nn = gs + t; nn < ge; nn += 256) lm = fmaxf(lm, gate[nn]);
    red[t] = lm; __syncthreads();
    for (int s2 = 128; s2 > 0; s2 >>= 1) {
        if (t < s2) red[t] = fmaxf(red[t], red[t + s2]);
        __syncthreads();
    }
    float m = red[0]; __syncthreads();
    float lsum = 0.f;
    for (int nn = gs + t; nn < ge; nn += 256) lsum += __expf(gate[nn] - m);
    red[t] = lsum; __syncthreads();
    for (int s2 = 128; s2 > 0; s2 >>= 1) {
        if (t < s2) red[t] += red[t + s2];
        __syncthreads();
    }
    if (t == 0) { gm[g] = m; ginv[g] = 1.f / (red[0] + 1e-16f); }
    pool[g * 256 + t] = 0.f;
}

__global__ void pool_acc_k(const __nv_bfloat16* __restrict__ ahi,
                           const __nv_bfloat16* __restrict__ alo,
                           const float* __restrict__ gate, const int* __restrict__ gstart,
                           const float* __restrict__ gm, const float* __restrict__ ginv,
                           float* __restrict__ pool) {
    int g = blockIdx.x;
    int part = blockIdx.y;
    int t = threadIdx.x;
    int gs = gstart[g], ge = gstart[g + 1];
    int len = ge - gs;
    int chunk = (len + 7) >> 3;
    int ns = gs + part * chunk;
    int ne = min(ns + chunk, ge);
    if (ns >= ne) return;
    float m = gm[g], inv = ginv[g];
    __shared__ float swt[256];
    float acc = 0.f;
    for (int cb = ns; cb < ne; cb += 256) {
        int nn = cb + t;
        swt[t] = (nn < ne) ? __expf(gate[nn] - m) * inv : 0.f;
        __syncthreads();
        int l2 = min(256, ne - cb);
        for (int i = 0; i < l2; i++) {
            size_t idx = (size_t)(cb + i) * 256 + t;
            acc += (__bfloat162float(ahi[idx]) + __bfloat162float(alo[idx])) * swt[i];
        }
        __syncthreads();
    }
    atomicAdd(&pool[g * 256 + t], acc);
}

__global__ void pool_fin_k(const float* __restrict__ pool, const float* __restrict__ cW1,
                           const float* __restrict__ cb1, const float* __restrict__ cW2,
                           const float* __restrict__ cb2, float* __restrict__ out) {
    int g = blockIdx.x;
    int t = threadIdx.x;
    __shared__ float pooled[256];
    __shared__ float tt[128];
    pooled[t] = pool[g * 256 + t];
    pooled[t + 128] = pool[g * 256 + t + 128];
    __syncthreads();
    float s1 = cb1[t];
#pragma unroll 4
    for (int c = 0; c < 256; c++) s1 += pooled[c] * cW1[c * 128 + t];
    tt[t] = fmaxf(s1, 0.f);
    __syncthreads();
    if (t < 2) {
        float o = cb2[t];
        for (int j = 0; j < 128; j++) o += tt[j] * cW2[j * 2 + t];
        out[g * 2 + t] = o;
    }
}

// ---------------- launch ----------------
extern "C" void kernel_launch(void* const* d_in, const int* in_sizes, int n_in,
                              void* d_out, int out_size) {
    const float* x    = (const float*)d_in[0];
    const int*   ei   = (const int*)  d_in[1];
    const int*   batch= (const int*)  d_in[2];
    const float* W0   = (const float*)d_in[3];
    const float* as0  = (const float*)d_in[4];
    const float* ad0  = (const float*)d_in[5];
    const float* b0   = (const float*)d_in[6];
    const float* gm0  = (const float*)d_in[7];
    const float* be0  = (const float*)d_in[8];
    const float* W1   = (const float*)d_in[9];
    const float* as1  = (const float*)d_in[10];
    const float* ad1  = (const float*)d_in[11];
    const float* b1   = (const float*)d_in[12];
    const float* gm1  = (const float*)d_in[13];
    const float* be1  = (const float*)d_in[14];
    const float* pW1  = (const float*)d_in[15];
    const float* pb1  = (const float*)d_in[16];
    const float* pW2  = (const float*)d_in[17];
    const float* pb2  = (const float*)d_in[18];
    const float* cW1  = (const float*)d_in[19];
    const float* cb1  = (const float*)d_in[20];
    const float* cW2  = (const float*)d_in[21];
    const float* cb2  = (const float*)d_in[22];
    float* out = (float*)d_out;

    int N = in_sizes[0] / 128;
    int E = in_sizes[1] / 2;

    float *als, *ald, *gate, *pool, *gmv, *ginv;
    __nv_bfloat16 *hbb, *ahi, *alo, *wt0h, *wt0l, *wt1h, *wt1l, *wtph, *wtpl;
    int *cnt, *off, *fill, *srcv, *gstart, *bsum;
    cudaGetSymbolAddress((void**)&hbb,   g_hb);
    cudaGetSymbolAddress((void**)&ahi,   g_ahi);
    cudaGetSymbolAddress((void**)&alo,   g_alo);
    cudaGetSymbolAddress((void**)&wt0h,  g_wt0hi);
    cudaGetSymbolAddress((void**)&wt0l,  g_wt0lo);
    cudaGetSymbolAddress((void**)&wt1h,  g_wt1hi);
    cudaGetSymbolAddress((void**)&wt1l,  g_wt1lo);
    cudaGetSymbolAddress((void**)&wtph,  g_wtphi);
    cudaGetSymbolAddress((void**)&wtpl,  g_wtplo);
    cudaGetSymbolAddress((void**)&als,   g_als);
    cudaGetSymbolAddress((void**)&ald,   g_ald);
    cudaGetSymbolAddress((void**)&gate,  g_gate);
    cudaGetSymbolAddress((void**)&pool,  g_pool);
    cudaGetSymbolAddress((void**)&gmv,   g_gm);
    cudaGetSymbolAddress((void**)&ginv,  g_ginv);
    cudaGetSymbolAddress((void**)&cnt,   g_cnt);
    cudaGetSymbolAddress((void**)&off,   g_off);
    cudaGetSymbolAddress((void**)&fill,  g_fill);
    cudaGetSymbolAddress((void**)&srcv,  g_srcv);
    cudaGetSymbolAddress((void**)&gstart,g_gstart);
    cudaGetSymbolAddress((void**)&bsum,  g_bsum);

    static cudaStream_t s2 = nullptr;
    static cudaEvent_t evFork = nullptr, evJoin = nullptr;
    static bool attr_done = false;
    if (!attr_done) {
        cudaFuncSetAttribute(gemm_mma_k<false>,
                             cudaFuncAttributeMaxDynamicSharedMemorySize, 2 * GSTG);
        cudaFuncSetAttribute(gemm_mma_k<true>,
                             cudaFuncAttributeMaxDynamicSharedMemorySize, 2 * GSTG);
        cudaStreamCreateWithFlags(&s2, cudaStreamNonBlocking);
        cudaEventCreateWithFlags(&evFork, cudaEventDisableTiming);
        cudaEventCreateWithFlags(&evJoin, cudaEventDisableTiming);
        attr_done = true;
    }

    int nb   = (N + 255) / 256;
    int ebk  = (E + 255) / 256;
    int wnb  = (N + 7) / 8;
    int nb1k = (N + 1023) / 1024;
    int gmx  = (N + 127) / 128;
    int npx  = (N * 128 + 255) / 256;

    cudaMemsetAsync(cnt, 0, N * sizeof(int));
    prep_k<<<npx, 256>>>(x, ahi, alo, N * 128, ei, E, cnt,
                         W0, wt0h, wt0l, W1, wt1h, wt1l, pW1, wtph, wtpl);

    // fork: CSR build on s2 concurrent with GEMM-0 on main stream
    cudaEventRecord(evFork, 0);
    cudaStreamWaitEvent(s2, evFork, 0);
    scan_block_k<<<nb1k, 1024, 0, s2>>>(cnt, off, bsum, N, batch, gstart, GI);
    scan_add_fill_k<<<nb, 256, 0, s2>>>(bsum, off, fill, srcv, N, nb1k);
    scatter_k<<<ebk, 256, 0, s2>>>(ei, E, fill, srcv);
    cudaEventRecord(evJoin, s2);

    gemm_mma_k<false><<<dim3(gmx, 2), 256, 2 * GSTG>>>(ahi, alo, wt0h, wt0l, hbb, als, ald,
                                                       as0, ad0, nullptr, nullptr, nullptr,
                                                       nullptr, N, 128, 256);
    cudaStreamWaitEvent(0, evJoin, 0);   // join before edge_agg

    edge_agg_k<<<wnb, 256>>>(off, srcv, hbb, als, ald, b0, gm0, be0, ahi, alo, N);
    gemm_mma_k<false><<<dim3(gmx, 2), 256, 2 * GSTG>>>(ahi, alo, wt1h, wt1l, hbb, als, ald,
                                                       as1, ad1, nullptr, nullptr, nullptr,
                                                       nullptr, N, 256, 256);
    edge_agg_k<<<wnb, 256>>>(off, srcv, hbb, als, ald, b1, gm1, be1, ahi, alo, N);
    gemm_mma_k<true><<<dim3(gmx, 1), 256, 2 * GSTG>>>(ahi, alo, wtph, wtpl, nullptr, nullptr,
                                                      nullptr, nullptr, nullptr, pb1, pW2,
                                                      pb2, gate, N, 256, 128);
    pool_stats_k<<<GI, 256>>>(gate, gstart, gmv, ginv, pool);
    pool_acc_k<<<dim3(GI, 8), 256>>>(ahi, alo, gate, gstart, gmv, ginv, pool);
    pool_fin_k<<<GI, 128>>>(pool, cW1, cb1, cW2, cb2, out);
}

// round 15
// speedup vs baseline: 1.0836x; 1.0836x over previous
#include <cuda_runtime.h>
#include <cuda_bf16.h>
#include <math.h>
#include <stdint.h>

#define NN 50000
#define EE 800000
#define GI 64
#define HCDIM 256

// ---------------- scratch (static device globals; no allocation) ----------------
__device__ __nv_bfloat16 g_hb[(size_t)NN * HCDIM];   // GEMM output h (bf16, gathered)
__device__ __nv_bfloat16 g_ahi[(size_t)NN * HCDIM];  // A operand hi
__device__ __nv_bfloat16 g_alo[(size_t)NN * HCDIM];  // A operand lo
__device__ __nv_bfloat16 g_wt0hi[256 * 128], g_wt0lo[256 * 128];
__device__ __nv_bfloat16 g_wt1hi[256 * 256], g_wt1lo[256 * 256];
__device__ __nv_bfloat16 g_wtphi[128 * 256], g_wtplo[128 * 256];
__device__ float g_als[NN * 4];
__device__ float g_ald[NN * 4];
__device__ float g_gate[NN];
__device__ float g_pool[GI * HCDIM];
__device__ float g_gm[GI];
__device__ float g_ginv[GI];
__device__ int   g_cnt[NN];
__device__ int   g_off[NN + 1];
__device__ int   g_fill[NN];
__device__ int   g_srcv[EE + NN];
__device__ int   g_gstart[GI + 1];
__device__ int   g_bsum[64];

// ---------------- helpers ----------------
__device__ __forceinline__ void mma_bf16(float* c, const uint32_t* a, const uint32_t* b) {
    asm volatile(
        "mma.sync.aligned.m16n8k16.row.col.f32.bf16.bf16.f32 "
        "{%0,%1,%2,%3}, {%4,%5,%6,%7}, {%8,%9}, {%0,%1,%2,%3};"
        : "+f"(c[0]), "+f"(c[1]), "+f"(c[2]), "+f"(c[3])
        : "r"(a[0]), "r"(a[1]), "r"(a[2]), "r"(a[3]), "r"(b[0]), "r"(b[1]));
}
#define LDM4(r, addr) \
    asm volatile("ldmatrix.sync.aligned.m8n8.x4.shared.b16 {%0,%1,%2,%3}, [%4];" \
        : "=r"((r)[0]), "=r"((r)[1]), "=r"((r)[2]), "=r"((r)[3]) : "r"(addr))
__device__ __forceinline__ uint32_t smem_u32(const void* p) {
    uint32_t a;
    asm("{ .reg .u64 t; cvta.to.shared.u64 t, %1; cvt.u32.u64 %0, t; }" : "=r"(a) : "l"(p));
    return a;
}
__device__ __forceinline__ void cpa16(uint32_t dst, const void* src, uint32_t sz) {
    asm volatile("cp.async.cg.shared.global [%0], [%1], 16, %2;"
                 :: "r"(dst), "l"(src), "r"(sz));
}
#define CP_COMMIT() asm volatile("cp.async.commit_group;")
#define CP_WAIT(n)  asm volatile("cp.async.wait_group %0;" :: "n"(n))
__device__ __forceinline__ uint32_t packbf(float a, float b) {
    return (uint32_t)__bfloat16_as_ushort(__float2bfloat16(a)) |
           ((uint32_t)__bfloat16_as_ushort(__float2bfloat16(b)) << 16);
}

// ---------------- fused prep: split x + edge count + all weight splits ----------
__global__ void prep_k(const float* __restrict__ x, __nv_bfloat16* xhi, __nv_bfloat16* xlo,
                       int nx, const int* __restrict__ ei, int E, int* cnt,
                       const float* __restrict__ W0, __nv_bfloat16* w0h, __nv_bfloat16* w0l,
                       const float* __restrict__ W1, __nv_bfloat16* w1h, __nv_bfloat16* w1l,
                       const float* __restrict__ pW1, __nv_bfloat16* wph, __nv_bfloat16* wpl) {
    int i = blockIdx.x * blockDim.x + threadIdx.x;
    if (i < nx) {
        float v = x[i];
        __nv_bfloat16 h = __float2bfloat16(v);
        xhi[i] = h;
        xlo[i] = __float2bfloat16(v - __bfloat162float(h));
    }
    if (i < E) atomicAdd(&cnt[ei[E + i]], 1);
    if (i < 128 * 256) {
        int k = i >> 8, n = i & 255;
        float v = W0[i];
        __nv_bfloat16 h = __float2bfloat16(v);
        w0h[n * 128 + k] = h;
        w0l[n * 128 + k] = __float2bfloat16(v - __bfloat162float(h));
    }
    if (i < 256 * 256) {
        int k = i >> 8, n = i & 255;
        float v = W1[i];
        __nv_bfloat16 h = __float2bfloat16(v);
        w1h[n * 256 + k] = h;
        w1l[n * 256 + k] = __float2bfloat16(v - __bfloat162float(h));
    }
    if (i < 256 * 128) {
        int k = i >> 7, n = i & 127;
        float v = pW1[i];
        __nv_bfloat16 h = __float2bfloat16(v);
        wph[n * 256 + k] = h;
        wpl[n * 256 + k] = __float2bfloat16(v - __bfloat162float(h));
    }
}

// ---------------- CSR scan (+fused gstart) ----------------
__global__ void scan_block_k(const int* __restrict__ cnt, int* __restrict__ off,
                             int* __restrict__ bsum, int n,
                             const int* __restrict__ batch, int* __restrict__ gstart, int G) {
    int i = blockIdx.x * 1024 + threadIdx.x;
    int lane = threadIdx.x & 31, wid = threadIdx.x >> 5;
    int v = (i < n) ? cnt[i] + 1 : 0;   // +1 = self loop
    int s = v;
#pragma unroll
    for (int d = 1; d < 32; d <<= 1) {
        int t = __shfl_up_sync(0xffffffffu, s, d);
        if (lane >= d) s += t;
    }
    __shared__ int wsum[32];
    if (lane == 31) wsum[wid] = s;
    __syncthreads();
    if (wid == 0) {
        int w = wsum[lane];
#pragma unroll
        for (int d = 1; d < 32; d <<= 1) {
            int t = __shfl_up_sync(0xffffffffu, w, d);
            if (lane >= d) w += t;
        }
        wsum[lane] = w;
    }
    __syncthreads();
    int base = wid ? wsum[wid - 1] : 0;
    if (i < n) off[i] = base + s - v;
    if (threadIdx.x == 1023) bsum[blockIdx.x] = base + s;
    if (i < n) {
        int b = batch[i];
        if (i == 0) { for (int g = 0; g <= b; g++) gstart[g] = 0; }
        else {
            int pb = batch[i - 1];
            if (pb != b) for (int g = pb + 1; g <= b; g++) gstart[g] = i;
        }
        if (i == n - 1) for (int g = b + 1; g <= G; g++) gstart[g] = n;
    }
}
__global__ void scan_add_fill_k(const int* __restrict__ bsum, int* __restrict__ off,
                                int* __restrict__ fill, int* __restrict__ srcv,
                                int n, int nb) {
    __shared__ int sh[64];
    int t = threadIdx.x;   // 256
    if (t < 64) sh[t] = (t < nb) ? bsum[t] : 0;
    __syncthreads();
#pragma unroll
    for (int d = 1; d < 64; d <<= 1) {
        int x = (t >= d && t < 64) ? sh[t - d] : 0;
        __syncthreads();
        if (t < 64) sh[t] += x;
        __syncthreads();
    }
    int i = blockIdx.x * 256 + t;
    if (i < n) {
        int b = i >> 10;
        int o = off[i] + (b ? sh[b - 1] : 0);
        off[i] = o;
        fill[i] = o + 1;
        srcv[o] = i;
    }
    if (blockIdx.x == 0 && t == 0) off[n] = sh[nb - 1];
}
__global__ void scatter_k(const int* __restrict__ ei, int E, int* fill, int* srcv) {
    int e = blockIdx.x * blockDim.x + threadIdx.x;
    if (e < E) {
        int s = ei[e];
        int d = ei[E + e];
        int p = atomicAdd(&fill[d], 1);
        srcv[p] = s;
    }
}

// ---------------- HMMA GEMM with cp.async double buffering --------------------
// GATE=true: A operand is hi-only (2 MMA terms) — terminal path, error attenuates.
#define GSTG 40960
#define OFF_AH 0
#define OFF_AL 10240
#define OFF_BH 20480
#define OFF_BL 30720
template <bool GATE>
__global__ __launch_bounds__(256, 2)
void gemm_mma_k(const __nv_bfloat16* __restrict__ ahi, const __nv_bfloat16* __restrict__ alo,
                const __nv_bfloat16* __restrict__ bhi, const __nv_bfloat16* __restrict__ blo,
                __nv_bfloat16* __restrict__ Cb, float* __restrict__ als, float* __restrict__ ald,
                const float* __restrict__ asrc, const float* __restrict__ adst,
                const float* __restrict__ pb1, const float* __restrict__ pW2,
                const float* __restrict__ pb2, float* __restrict__ gate,
                int M, int K, int NTT) {
    extern __shared__ char dynsm[];
    __shared__ float sgate[128];
    uint32_t sbase = smem_u32(dynsm);

    int tid = threadIdx.x;
    int wid = tid >> 5, lane = tid & 31;
    int wr = wid >> 1, wc = wid & 1;
    int row0 = blockIdx.x * 128;
    int nbase = blockIdx.y * 128;

    float acc[2][8][4];
#pragma unroll
    for (int mt = 0; mt < 2; mt++)
#pragma unroll
        for (int nt = 0; nt < 8; nt++)
#pragma unroll
            for (int q = 0; q < 4; q++) acc[mt][nt][q] = 0.f;

    int r4 = lane >> 2, k2 = (lane & 3) * 2;
    uint32_t aoffB = (uint32_t)(((wr * 32 + (lane & 15)) * 40 + (lane >> 4) * 8) * 2);
    uint32_t boffB = (uint32_t)(((wc * 64 + ((lane >> 4) & 1) * 8 + (lane & 7)) * 40 +
                                 ((lane >> 3) & 1) * 8) * 2);

    int ntiles = K >> 5;
    auto issue = [&](int kt) {
        uint32_t sb2 = sbase + (uint32_t)(kt & 1) * GSTG;
        int kbase = kt << 5;
#pragma unroll
        for (int i = 0; i < 2; i++) {
            int idx = tid + i * 256;
            int r = idx >> 2, q = idx & 3;
            int row = row0 + r;
            uint32_t doff = (uint32_t)((r * 40 + q * 8) * 2);
            size_t ga = (size_t)row * K + kbase + q * 8;
            uint32_t sz = (row < M) ? 16u : 0u;
            cpa16(sb2 + OFF_AH + doff, ahi + ga, sz);
            if constexpr (!GATE) cpa16(sb2 + OFF_AL + doff, alo + ga, sz);
            size_t gb = (size_t)(nbase + r) * K + kbase + q * 8;
            cpa16(sb2 + OFF_BH + doff, bhi + gb, 16u);
            cpa16(sb2 + OFF_BL + doff, blo + gb, 16u);
        }
        CP_COMMIT();
    };

    issue(0);
    for (int kt = 0; kt < ntiles; kt++) {
        if (kt + 1 < ntiles) { issue(kt + 1); CP_WAIT(1); }
        else                 { CP_WAIT(0); }
        __syncthreads();
        uint32_t sb2 = sbase + (uint32_t)(kt & 1) * GSTG;
#pragma unroll
        for (int kk = 0; kk < 32; kk += 16) {
            uint32_t a_h[2][4], a_l[2][4];
            uint32_t ab = aoffB + kk * 2;
            LDM4(a_h[0], sb2 + OFF_AH + ab);
            LDM4(a_h[1], sb2 + OFF_AH + ab + 16 * 80);
            if constexpr (!GATE) {
                LDM4(a_l[0], sb2 + OFF_AL + ab);
                LDM4(a_l[1], sb2 + OFF_AL + ab + 16 * 80);
            }
#pragma unroll
            for (int nh = 0; nh < 2; nh++) {
                uint32_t b_h[4][2], b_l[4][2];
                uint32_t bb = boffB + (nh * 32 * 40 + kk) * 2;
                uint32_t t0[4], t1[4];
                LDM4(t0, sb2 + OFF_BH + bb);
                LDM4(t1, sb2 + OFF_BH + bb + 16 * 80);
                b_h[0][0] = t0[0]; b_h[0][1] = t0[1]; b_h[1][0] = t0[2]; b_h[1][1] = t0[3];
                b_h[2][0] = t1[0]; b_h[2][1] = t1[1]; b_h[3][0] = t1[2]; b_h[3][1] = t1[3];
                LDM4(t0, sb2 + OFF_BL + bb);
                LDM4(t1, sb2 + OFF_BL + bb + 16 * 80);
                b_l[0][0] = t0[0]; b_l[0][1] = t0[1]; b_l[1][0] = t0[2]; b_l[1][1] = t0[3];
                b_l[2][0] = t1[0]; b_l[2][1] = t1[1]; b_l[3][0] = t1[2]; b_l[3][1] = t1[3];
#pragma unroll
                for (int mt = 0; mt < 2; mt++)
#pragma unroll
                    for (int j = 0; j < 4; j++) {
                        float* cc = acc[mt][nh * 4 + j];
                        mma_bf16(cc, a_h[mt], b_h[j]);
                        mma_bf16(cc, a_h[mt], b_l[j]);
                        if constexpr (!GATE) mma_bf16(cc, a_l[mt], b_h[j]);
                    }
            }
        }
        __syncthreads();
    }

    if constexpr (!GATE) {
        int hd = blockIdx.y * 2 + wc;
#pragma unroll
        for (int mt = 0; mt < 2; mt++) {
#pragma unroll
            for (int half = 0; half < 2; half++) {
                int row = row0 + wr * 32 + mt * 16 + r4 + half * 8;
                float ps = 0.f, pd = 0.f;
#pragma unroll
                for (int nt = 0; nt < 8; nt++) {
                    float c0 = acc[mt][nt][half * 2 + 0];
                    float c1 = acc[mt][nt][half * 2 + 1];
                    int gc = nbase + wc * 64 + nt * 8 + k2;
                    if (row < M)
                        *(uint32_t*)(Cb + (size_t)row * NTT + gc) = packbf(c0, c1);
                    ps += c0 * asrc[gc] + c1 * asrc[gc + 1];
                    pd += c0 * adst[gc] + c1 * adst[gc + 1];
                }
                ps += __shfl_xor_sync(0xffffffffu, ps, 1);
                ps += __shfl_xor_sync(0xffffffffu, ps, 2);
                pd += __shfl_xor_sync(0xffffffffu, pd, 1);
                pd += __shfl_xor_sync(0xffffffffu, pd, 2);
                if (row < M && (lane & 3) == 0) {
                    als[row * 4 + hd] = ps;
                    ald[row * 4 + hd] = pd;
                }
            }
        }
    } else {
        if (tid < 128) sgate[tid] = 0.f;
        __syncthreads();
#pragma unroll
        for (int mt = 0; mt < 2; mt++) {
#pragma unroll
            for (int half = 0; half < 2; half++) {
                int rl = wr * 32 + mt * 16 + r4 + half * 8;
                float p = 0.f;
#pragma unroll
                for (int nt = 0; nt < 8; nt++) {
                    float c0 = acc[mt][nt][half * 2 + 0];
                    float c1 = acc[mt][nt][half * 2 + 1];
                    int gc = wc * 64 + nt * 8 + k2;
                    p += fmaxf(c0 + pb1[gc], 0.f) * pW2[gc];
                    p += fmaxf(c1 + pb1[gc + 1], 0.f) * pW2[gc + 1];
                }
                p += __shfl_xor_sync(0xffffffffu, p, 1);
                p += __shfl_xor_sync(0xffffffffu, p, 2);
                if ((lane & 3) == 0) atomicAdd(&sgate[rl], p);
            }
        }
        __syncthreads();
        if (tid < 128) {
            int row = row0 + tid;
            if (row < M) gate[row] = sgate[tid] + pb2[0];
        }
    }
}

// ---------------- fused edge softmax + aggregate + bias + LN + ReLU ------------
// WLO=false: skip the lo-residual output stream (terminal layer).
__device__ __forceinline__ float lrelu(float x) { return x > 0.f ? x : 0.2f * x; }

template <bool WLO>
__global__ void edge_agg_k(const int* __restrict__ off, const int* __restrict__ csr,
                           const __nv_bfloat16* __restrict__ hb, const float* __restrict__ als,
                           const float* __restrict__ ald, const float* __restrict__ bias,
                           const float* __restrict__ gamma, const float* __restrict__ beta,
                           __nv_bfloat16* __restrict__ ohi, __nv_bfloat16* __restrict__ olo,
                           int n) {
    int node = (blockIdx.x * blockDim.x + threadIdx.x) >> 5;
    int lane = threadIdx.x & 31;
    if (node >= n) return;
    int beg = off[node], end = off[node + 1];

    int hd = lane >> 3;
    int eoff = lane & 7;
    float adh = ald[node * 4 + hd];

    float sexp = 0.f;
    float4 a0 = make_float4(0.f, 0.f, 0.f, 0.f);
    float4 a1 = make_float4(0.f, 0.f, 0.f, 0.f);
    for (int cb = beg; cb < end; cb += 8) {
        int cnt = min(8, end - cb);
        float ev = 0.f;
        int smine = 0;
        if (eoff < cnt) {
            smine = csr[cb + eoff];
            ev = __expf(lrelu(als[(size_t)smine * 4 + hd] + adh));
        }
        sexp += ev;
        int lbase = lane & 24;
        for (int e = 0; e < cnt; e++) {
            float w = __shfl_sync(0xffffffffu, ev, lbase + e);
            int se = __shfl_sync(0xffffffffu, smine, e);
            uint4 u = *(const uint4*)(hb + (size_t)se * 256 + lane * 8);
            float2 f0 = __bfloat1622float2(*(__nv_bfloat162*)&u.x);
            float2 f1 = __bfloat1622float2(*(__nv_bfloat162*)&u.y);
            float2 f2 = __bfloat1622float2(*(__nv_bfloat162*)&u.z);
            float2 f3 = __bfloat1622float2(*(__nv_bfloat162*)&u.w);
            a0.x += w * f0.x; a0.y += w * f0.y; a0.z += w * f1.x; a0.w += w * f1.y;
            a1.x += w * f2.x; a1.y += w * f2.y; a1.z += w * f3.x; a1.w += w * f3.y;
        }
    }
    sexp += __shfl_xor_sync(0xffffffffu, sexp, 1);
    sexp += __shfl_xor_sync(0xffffffffu, sexp, 2);
    sexp += __shfl_xor_sync(0xffffffffu, sexp, 4);
    float inv = 1.f / (sexp + 1e-16f);

    const float4* bp = (const float4*)(bias + lane * 8);
    float4 b0 = bp[0], b1 = bp[1];
    float y[8] = { a0.x * inv + b0.x, a0.y * inv + b0.y, a0.z * inv + b0.z, a0.w * inv + b0.w,
                   a1.x * inv + b1.x, a1.y * inv + b1.y, a1.z * inv + b1.z, a1.w * inv + b1.w };
    float ls = 0.f, lq = 0.f;
#pragma unroll
    for (int i = 0; i < 8; i++) { ls += y[i]; lq += y[i] * y[i]; }
#pragma unroll
    for (int o = 16; o > 0; o >>= 1) {
        ls += __shfl_xor_sync(0xffffffffu, ls, o);
        lq += __shfl_xor_sync(0xffffffffu, lq, o);
    }
    float mu  = ls * (1.f / 256.f);
    float var = lq * (1.f / 256.f) - mu * mu;
    float rs  = rsqrtf(var + 1e-5f);
    const float4* gp = (const float4*)(gamma + lane * 8);
    const float4* ep = (const float4*)(beta + lane * 8);
    float4 g0 = gp[0], g1 = gp[1], e0 = ep[0], e1 = ep[1];
    float o8[8];
    o8[0] = fmaxf((y[0] - mu) * rs * g0.x + e0.x, 0.f);
    o8[1] = fmaxf((y[1] - mu) * rs * g0.y + e0.y, 0.f);
    o8[2] = fmaxf((y[2] - mu) * rs * g0.z + e0.z, 0.f);
    o8[3] = fmaxf((y[3] - mu) * rs * g0.w + e0.w, 0.f);
    o8[4] = fmaxf((y[4] - mu) * rs * g1.x + e1.x, 0.f);
    o8[5] = fmaxf((y[5] - mu) * rs * g1.y + e1.y, 0.f);
    o8[6] = fmaxf((y[6] - mu) * rs * g1.z + e1.z, 0.f);
    o8[7] = fmaxf((y[7] - mu) * rs * g1.w + e1.w, 0.f);

    uint4 uh;
    uh.x = packbf(o8[0], o8[1]); uh.y = packbf(o8[2], o8[3]);
    uh.z = packbf(o8[4], o8[5]); uh.w = packbf(o8[6], o8[7]);
    ((uint4*)ohi)[(size_t)node * 32 + lane] = uh;
    if constexpr (WLO) {
        float r8[8];
#pragma unroll
        for (int i = 0; i < 8; i++) {
            __nv_bfloat16 hbv = __float2bfloat16(o8[i]);
            r8[i] = o8[i] - __bfloat162float(hbv);
        }
        uint4 ul;
        ul.x = packbf(r8[0], r8[1]); ul.y = packbf(r8[2], r8[3]);
        ul.z = packbf(r8[4], r8[5]); ul.w = packbf(r8[6], r8[7]);
        ((uint4*)olo)[(size_t)node * 32 + lane] = ul;
    }
}

// ---------------- pooling: stats -> parallel accumulate -> classifier ----------
__global__ void pool_stats_k(const float* __restrict__ gate, const int* __restrict__ gstart,
                             float* __restrict__ gm, float* __restrict__ ginv,
                             float* __restrict__ pool) {
    int g = blockIdx.x;
    int t = threadIdx.x;
    int gs = gstart[g], ge = gstart[g + 1];
    __shared__ float red[256];
    float lm = -1e30f;
    for (int nn = gs + t; nn < ge; nn += 256) lm = fmaxf(lm, gate[nn]);
    red[t] = lm; __syncthreads();
    for (int s2 = 128; s2 > 0; s2 >>= 1) {
        if (t < s2) red[t] = fmaxf(red[t], red[t + s2]);
        __syncthreads();
    }
    float m = red[0]; __syncthreads();
    float lsum = 0.f;
    for (int nn = gs + t; nn < ge; nn += 256) lsum += __expf(gate[nn] - m);
    red[t] = lsum; __syncthreads();
    for (int s2 = 128; s2 > 0; s2 >>= 1) {
        if (t < s2) red[t] += red[t + s2];
        __syncthreads();
    }
    if (t == 0) { gm[g] = m; ginv[g] = 1.f / (red[0] + 1e-16f); }
    pool[g * 256 + t] = 0.f;
}

__global__ void pool_acc_k(const __nv_bfloat16* __restrict__ ahi,
                           const float* __restrict__ gate, const int* __restrict__ gstart,
                           const float* __restrict__ gm, const float* __restrict__ ginv,
                           float* __restrict__ pool) {
    int g = blockIdx.x;
    int part = blockIdx.y;
    int t = threadIdx.x;
    int gs = gstart[g], ge = gstart[g + 1];
    int len = ge - gs;
    int chunk = (len + 7) >> 3;
    int ns = gs + part * chunk;
    int ne = min(ns + chunk, ge);
    if (ns >= ne) return;
    float m = gm[g], inv = ginv[g];
    __shared__ float swt[256];
    float acc = 0.f;
    for (int cb = ns; cb < ne; cb += 256) {
        int nn = cb + t;
        swt[t] = (nn < ne) ? __expf(gate[nn] - m) * inv : 0.f;
        __syncthreads();
        int l2 = min(256, ne - cb);
        for (int i = 0; i < l2; i++) {
            size_t idx = (size_t)(cb + i) * 256 + t;
            acc += __bfloat162float(ahi[idx]) * swt[i];
        }
        __syncthreads();
    }
    atomicAdd(&pool[g * 256 + t], acc);
}

__global__ void pool_fin_k(const float* __restrict__ pool, const float* __restrict__ cW1,
                           const float* __restrict__ cb1, const float* __restrict__ cW2,
                           const float* __restrict__ cb2, float* __restrict__ out) {
    int g = blockIdx.x;
    int t = threadIdx.x;
    __shared__ float pooled[256];
    __shared__ float tt[128];
    pooled[t] = pool[g * 256 + t];
    pooled[t + 128] = pool[g * 256 + t + 128];
    __syncthreads();
    float s1 = cb1[t];
#pragma unroll 4
    for (int c = 0; c < 256; c++) s1 += pooled[c] * cW1[c * 128 + t];
    tt[t] = fmaxf(s1, 0.f);
    __syncthreads();
    if (t < 2) {
        float o = cb2[t];
        for (int j = 0; j < 128; j++) o += tt[j] * cW2[j * 2 + t];
        out[g * 2 + t] = o;
    }
}

// ---------------- launch ----------------
extern "C" void kernel_launch(void* const* d_in, const int* in_sizes, int n_in,
                              void* d_out, int out_size) {
    const float* x    = (const float*)d_in[0];
    const int*   ei   = (const int*)  d_in[1];
    const int*   batch= (const int*)  d_in[2];
    const float* W0   = (const float*)d_in[3];
    const float* as0  = (const float*)d_in[4];
    const float* ad0  = (const float*)d_in[5];
    const float* b0   = (const float*)d_in[6];
    const float* gm0  = (const float*)d_in[7];
    const float* be0  = (const float*)d_in[8];
    const float* W1   = (const float*)d_in[9];
    const float* as1  = (const float*)d_in[10];
    const float* ad1  = (const float*)d_in[11];
    const float* b1   = (const float*)d_in[12];
    const float* gm1  = (const float*)d_in[13];
    const float* be1  = (const float*)d_in[14];
    const float* pW1  = (const float*)d_in[15];
    const float* pb1  = (const float*)d_in[16];
    const float* pW2  = (const float*)d_in[17];
    const float* pb2  = (const float*)d_in[18];
    const float* cW1  = (const float*)d_in[19];
    const float* cb1  = (const float*)d_in[20];
    const float* cW2  = (const float*)d_in[21];
    const float* cb2  = (const float*)d_in[22];
    float* out = (float*)d_out;

    int N = in_sizes[0] / 128;
    int E = in_sizes[1] / 2;

    float *als, *ald, *gate, *pool, *gmv, *ginv;
    __nv_bfloat16 *hbb, *ahi, *alo, *wt0h, *wt0l, *wt1h, *wt1l, *wtph, *wtpl;
    int *cnt, *off, *fill, *srcv, *gstart, *bsum;
    cudaGetSymbolAddress((void**)&hbb,   g_hb);
    cudaGetSymbolAddress((void**)&ahi,   g_ahi);
    cudaGetSymbolAddress((void**)&alo,   g_alo);
    cudaGetSymbolAddress((void**)&wt0h,  g_wt0hi);
    cudaGetSymbolAddress((void**)&wt0l,  g_wt0lo);
    cudaGetSymbolAddress((void**)&wt1h,  g_wt1hi);
    cudaGetSymbolAddress((void**)&wt1l,  g_wt1lo);
    cudaGetSymbolAddress((void**)&wtph,  g_wtphi);
    cudaGetSymbolAddress((void**)&wtpl,  g_wtplo);
    cudaGetSymbolAddress((void**)&als,   g_als);
    cudaGetSymbolAddress((void**)&ald,   g_ald);
    cudaGetSymbolAddress((void**)&gate,  g_gate);
    cudaGetSymbolAddress((void**)&pool,  g_pool);
    cudaGetSymbolAddress((void**)&gmv,   g_gm);
    cudaGetSymbolAddress((void**)&ginv,  g_ginv);
    cudaGetSymbolAddress((void**)&cnt,   g_cnt);
    cudaGetSymbolAddress((void**)&off,   g_off);
    cudaGetSymbolAddress((void**)&fill,  g_fill);
    cudaGetSymbolAddress((void**)&srcv,  g_srcv);
    cudaGetSymbolAddress((void**)&gstart,g_gstart);
    cudaGetSymbolAddress((void**)&bsum,  g_bsum);

    static cudaStream_t s2 = nullptr;
    static cudaEvent_t evFork = nullptr, evJoin = nullptr;
    static bool attr_done = false;
    if (!attr_done) {
        cudaFuncSetAttribute(gemm_mma_k<false>,
                             cudaFuncAttributeMaxDynamicSharedMemorySize, 2 * GSTG);
        cudaFuncSetAttribute(gemm_mma_k<true>,
                             cudaFuncAttributeMaxDynamicSharedMemorySize, 2 * GSTG);
        cudaStreamCreateWithFlags(&s2, cudaStreamNonBlocking);
        cudaEventCreateWithFlags(&evFork, cudaEventDisableTiming);
        cudaEventCreateWithFlags(&evJoin, cudaEventDisableTiming);
        attr_done = true;
    }

    int nb   = (N + 255) / 256;
    int ebk  = (E + 255) / 256;
    int wnb  = (N + 7) / 8;
    int nb1k = (N + 1023) / 1024;
    int gmx  = (N + 127) / 128;
    int npx  = (N * 128 + 255) / 256;

    cudaMemsetAsync(cnt, 0, N * sizeof(int));
    prep_k<<<npx, 256>>>(x, ahi, alo, N * 128, ei, E, cnt,
                         W0, wt0h, wt0l, W1, wt1h, wt1l, pW1, wtph, wtpl);

    // fork: CSR build on s2 concurrent with GEMM-0 on main stream
    cudaEventRecord(evFork, 0);
    cudaStreamWaitEvent(s2, evFork, 0);
    scan_block_k<<<nb1k, 1024, 0, s2>>>(cnt, off, bsum, N, batch, gstart, GI);
    scan_add_fill_k<<<nb, 256, 0, s2>>>(bsum, off, fill, srcv, N, nb1k);
    scatter_k<<<ebk, 256, 0, s2>>>(ei, E, fill, srcv);
    cudaEventRecord(evJoin, s2);

    gemm_mma_k<false><<<dim3(gmx, 2), 256, 2 * GSTG>>>(ahi, alo, wt0h, wt0l, hbb, als, ald,
                                                       as0, ad0, nullptr, nullptr, nullptr,
                                                       nullptr, N, 128, 256);
    cudaStreamWaitEvent(0, evJoin, 0);   // join before edge_agg

    // layer 0: full hi/lo output (feeds accuracy-critical GEMM-1)
    edge_agg_k<true><<<wnb, 256>>>(off, srcv, hbb, als, ald, b0, gm0, be0, ahi, alo, N);
    gemm_mma_k<false><<<dim3(gmx, 2), 256, 2 * GSTG>>>(ahi, alo, wt1h, wt1l, hbb, als, ald,
                                                       as1, ad1, nullptr, nullptr, nullptr,
                                                       nullptr, N, 256, 256);
    // layer 1: hi-only output (terminal path; error attenuates through pooling)
    edge_agg_k<false><<<wnb, 256>>>(off, srcv, hbb, als, ald, b1, gm1, be1, ahi, nullptr, N);
    // gate GEMM: A = hi only (2 MMA terms)
    gemm_mma_k<true><<<dim3(gmx, 1), 256, 2 * GSTG>>>(ahi, nullptr, wtph, wtpl, nullptr, nullptr,
                                                      nullptr, nullptr, nullptr, pb1, pW2,
                                                      pb2, gate, N, 256, 128);
    pool_stats_k<<<GI, 256>>>(gate, gstart, gmv, ginv, pool);
    pool_acc_k<<<dim3(GI, 8), 256>>>(ahi, gate, gstart, gmv, ginv, pool);
    pool_fin_k<<<GI, 128>>>(pool, cW1, cb1, cW2, cb2, out);
}

// round 16
// speedup vs baseline: 1.1788x; 1.0878x over previous
#include <cuda_runtime.h>
#include <cuda_bf16.h>
#include <math.h>
#include <stdint.h>

#define NN 50000
#define EE 800000
#define GI 64
#define HCDIM 256

// ---------------- scratch (static device globals; no allocation) ----------------
__device__ __nv_bfloat16 g_hb[(size_t)NN * HCDIM];   // GEMM output h (bf16, gathered)
__device__ __nv_bfloat16 g_ahi[(size_t)NN * HCDIM];  // A operand (bf16)
__device__ __nv_bfloat16 g_wt0hi[256 * 128], g_wt0lo[256 * 128];
__device__ __nv_bfloat16 g_wt1hi[256 * 256], g_wt1lo[256 * 256];
__device__ __nv_bfloat16 g_wtphi[128 * 256], g_wtplo[128 * 256];
__device__ float g_als[NN * 4];
__device__ float g_ald[NN * 4];
__device__ float g_gate[NN];
__device__ float g_pool[GI * HCDIM];
__device__ float g_gm[GI];
__device__ float g_ginv[GI];
__device__ int   g_cnt[NN];
__device__ int   g_off[NN + 1];
__device__ int   g_fill[NN];
__device__ int   g_srcv[EE + NN];
__device__ int   g_gstart[GI + 1];
__device__ int   g_bsum[64];

// ---------------- helpers ----------------
__device__ __forceinline__ void mma_bf16(float* c, const uint32_t* a, const uint32_t* b) {
    asm volatile(
        "mma.sync.aligned.m16n8k16.row.col.f32.bf16.bf16.f32 "
        "{%0,%1,%2,%3}, {%4,%5,%6,%7}, {%8,%9}, {%0,%1,%2,%3};"
        : "+f"(c[0]), "+f"(c[1]), "+f"(c[2]), "+f"(c[3])
        : "r"(a[0]), "r"(a[1]), "r"(a[2]), "r"(a[3]), "r"(b[0]), "r"(b[1]));
}
#define LDM4(r, addr) \
    asm volatile("ldmatrix.sync.aligned.m8n8.x4.shared.b16 {%0,%1,%2,%3}, [%4];" \
        : "=r"((r)[0]), "=r"((r)[1]), "=r"((r)[2]), "=r"((r)[3]) : "r"(addr))
__device__ __forceinline__ uint32_t smem_u32(const void* p) {
    uint32_t a;
    asm("{ .reg .u64 t; cvta.to.shared.u64 t, %1; cvt.u32.u64 %0, t; }" : "=r"(a) : "l"(p));
    return a;
}
__device__ __forceinline__ void cpa16(uint32_t dst, const void* src, uint32_t sz) {
    asm volatile("cp.async.cg.shared.global [%0], [%1], 16, %2;"
                 :: "r"(dst), "l"(src), "r"(sz));
}
#define CP_COMMIT() asm volatile("cp.async.commit_group;")
#define CP_WAIT(n)  asm volatile("cp.async.wait_group %0;" :: "n"(n))
__device__ __forceinline__ uint32_t packbf(float a, float b) {
    return (uint32_t)__bfloat16_as_ushort(__float2bfloat16(a)) |
           ((uint32_t)__bfloat16_as_ushort(__float2bfloat16(b)) << 16);
}

// ---------------- fused prep: x->bf16 + edge count + weight splits -------------
__global__ void prep_k(const float* __restrict__ x, __nv_bfloat16* xhi, int nx,
                       const int* __restrict__ ei, int E, int* cnt,
                       const float* __restrict__ W0, __nv_bfloat16* w0h, __nv_bfloat16* w0l,
                       const float* __restrict__ W1, __nv_bfloat16* w1h, __nv_bfloat16* w1l,
                       const float* __restrict__ pW1, __nv_bfloat16* wph, __nv_bfloat16* wpl) {
    int i = blockIdx.x * blockDim.x + threadIdx.x;
    if (i < nx) xhi[i] = __float2bfloat16(x[i]);
    if (i < E) atomicAdd(&cnt[ei[E + i]], 1);
    if (i < 128 * 256) {
        int k = i >> 8, n = i & 255;
        float v = W0[i];
        __nv_bfloat16 h = __float2bfloat16(v);
        w0h[n * 128 + k] = h;
        w0l[n * 128 + k] = __float2bfloat16(v - __bfloat162float(h));
    }
    if (i < 256 * 256) {
        int k = i >> 8, n = i & 255;
        float v = W1[i];
        __nv_bfloat16 h = __float2bfloat16(v);
        w1h[n * 256 + k] = h;
        w1l[n * 256 + k] = __float2bfloat16(v - __bfloat162float(h));
    }
    if (i < 256 * 128) {
        int k = i >> 7, n = i & 127;
        float v = pW1[i];
        __nv_bfloat16 h = __float2bfloat16(v);
        wph[n * 256 + k] = h;
        wpl[n * 256 + k] = __float2bfloat16(v - __bfloat162float(h));
    }
}

// ---------------- CSR scan (+fused gstart) ----------------
__global__ void scan_block_k(const int* __restrict__ cnt, int* __restrict__ off,
                             int* __restrict__ bsum, int n,
                             const int* __restrict__ batch, int* __restrict__ gstart, int G) {
    int i = blockIdx.x * 1024 + threadIdx.x;
    int lane = threadIdx.x & 31, wid = threadIdx.x >> 5;
    int v = (i < n) ? cnt[i] + 1 : 0;   // +1 = self loop
    int s = v;
#pragma unroll
    for (int d = 1; d < 32; d <<= 1) {
        int t = __shfl_up_sync(0xffffffffu, s, d);
        if (lane >= d) s += t;
    }
    __shared__ int wsum[32];
    if (lane == 31) wsum[wid] = s;
    __syncthreads();
    if (wid == 0) {
        int w = wsum[lane];
#pragma unroll
        for (int d = 1; d < 32; d <<= 1) {
            int t = __shfl_up_sync(0xffffffffu, w, d);
            if (lane >= d) w += t;
        }
        wsum[lane] = w;
    }
    __syncthreads();
    int base = wid ? wsum[wid - 1] : 0;
    if (i < n) off[i] = base + s - v;
    if (threadIdx.x == 1023) bsum[blockIdx.x] = base + s;
    if (i < n) {
        int b = batch[i];
        if (i == 0) { for (int g = 0; g <= b; g++) gstart[g] = 0; }
        else {
            int pb = batch[i - 1];
            if (pb != b) for (int g = pb + 1; g <= b; g++) gstart[g] = i;
        }
        if (i == n - 1) for (int g = b + 1; g <= G; g++) gstart[g] = n;
    }
}
__global__ void scan_add_fill_k(const int* __restrict__ bsum, int* __restrict__ off,
                                int* __restrict__ fill, int* __restrict__ srcv,
                                int n, int nb) {
    __shared__ int sh[64];
    int t = threadIdx.x;   // 256
    if (t < 64) sh[t] = (t < nb) ? bsum[t] : 0;
    __syncthreads();
#pragma unroll
    for (int d = 1; d < 64; d <<= 1) {
        int x = (t >= d && t < 64) ? sh[t - d] : 0;
        __syncthreads();
        if (t < 64) sh[t] += x;
        __syncthreads();
    }
    int i = blockIdx.x * 256 + t;
    if (i < n) {
        int b = i >> 10;
        int o = off[i] + (b ? sh[b - 1] : 0);
        off[i] = o;
        fill[i] = o + 1;
        srcv[o] = i;
    }
    if (blockIdx.x == 0 && t == 0) off[n] = sh[nb - 1];
}
__global__ void scatter_k(const int* __restrict__ ei, int E, int* fill, int* srcv) {
    int e = blockIdx.x * blockDim.x + threadIdx.x;
    if (e < E) {
        int s = ei[e];
        int d = ei[E + e];
        int p = atomicAdd(&fill[d], 1);
        srcv[p] = s;
    }
}

// ---------------- HMMA GEMM: A bf16, B = hi+lo (weight correction kept) --------
// D = A·Bh + A·Bl. 2 MMA terms.
#define GSTG 30720
#define OFF_AH 0
#define OFF_BH 10240
#define OFF_BL 20480
template <bool GATE>
__global__ __launch_bounds__(256, 2)
void gemm_mma_k(const __nv_bfloat16* __restrict__ ahi,
                const __nv_bfloat16* __restrict__ bhi, const __nv_bfloat16* __restrict__ blo,
                __nv_bfloat16* __restrict__ Cb, float* __restrict__ als, float* __restrict__ ald,
                const float* __restrict__ asrc, const float* __restrict__ adst,
                const float* __restrict__ pb1, const float* __restrict__ pW2,
                const float* __restrict__ pb2, float* __restrict__ gate,
                int M, int K, int NTT) {
    extern __shared__ char dynsm[];
    __shared__ float sgate[128];
    uint32_t sbase = smem_u32(dynsm);

    int tid = threadIdx.x;
    int wid = tid >> 5, lane = tid & 31;
    int wr = wid >> 1, wc = wid & 1;
    int row0 = blockIdx.x * 128;
    int nbase = blockIdx.y * 128;

    float acc[2][8][4];
#pragma unroll
    for (int mt = 0; mt < 2; mt++)
#pragma unroll
        for (int nt = 0; nt < 8; nt++)
#pragma unroll
            for (int q = 0; q < 4; q++) acc[mt][nt][q] = 0.f;

    int r4 = lane >> 2, k2 = (lane & 3) * 2;
    uint32_t aoffB = (uint32_t)(((wr * 32 + (lane & 15)) * 40 + (lane >> 4) * 8) * 2);
    uint32_t boffB = (uint32_t)(((wc * 64 + ((lane >> 4) & 1) * 8 + (lane & 7)) * 40 +
                                 ((lane >> 3) & 1) * 8) * 2);

    int ntiles = K >> 5;
    auto issue = [&](int kt) {
        uint32_t sb2 = sbase + (uint32_t)(kt & 1) * GSTG;
        int kbase = kt << 5;
#pragma unroll
        for (int i = 0; i < 2; i++) {
            int idx = tid + i * 256;
            int r = idx >> 2, q = idx & 3;
            int row = row0 + r;
            uint32_t doff = (uint32_t)((r * 40 + q * 8) * 2);
            size_t ga = (size_t)row * K + kbase + q * 8;
            uint32_t sz = (row < M) ? 16u : 0u;
            cpa16(sb2 + OFF_AH + doff, ahi + ga, sz);
            size_t gb = (size_t)(nbase + r) * K + kbase + q * 8;
            cpa16(sb2 + OFF_BH + doff, bhi + gb, 16u);
            cpa16(sb2 + OFF_BL + doff, blo + gb, 16u);
        }
        CP_COMMIT();
    };

    issue(0);
    for (int kt = 0; kt < ntiles; kt++) {
        if (kt + 1 < ntiles) { issue(kt + 1); CP_WAIT(1); }
        else                 { CP_WAIT(0); }
        __syncthreads();
        uint32_t sb2 = sbase + (uint32_t)(kt & 1) * GSTG;
#pragma unroll
        for (int kk = 0; kk < 32; kk += 16) {
            uint32_t a_h[2][4];
            uint32_t ab = aoffB + kk * 2;
            LDM4(a_h[0], sb2 + OFF_AH + ab);
            LDM4(a_h[1], sb2 + OFF_AH + ab + 16 * 80);
#pragma unroll
            for (int nh = 0; nh < 2; nh++) {
                uint32_t b_h[4][2], b_l[4][2];
                uint32_t bb = boffB + (nh * 32 * 40 + kk) * 2;
                uint32_t t0[4], t1[4];
                LDM4(t0, sb2 + OFF_BH + bb);
                LDM4(t1, sb2 + OFF_BH + bb + 16 * 80);
                b_h[0][0] = t0[0]; b_h[0][1] = t0[1]; b_h[1][0] = t0[2]; b_h[1][1] = t0[3];
                b_h[2][0] = t1[0]; b_h[2][1] = t1[1]; b_h[3][0] = t1[2]; b_h[3][1] = t1[3];
                LDM4(t0, sb2 + OFF_BL + bb);
                LDM4(t1, sb2 + OFF_BL + bb + 16 * 80);
                b_l[0][0] = t0[0]; b_l[0][1] = t0[1]; b_l[1][0] = t0[2]; b_l[1][1] = t0[3];
                b_l[2][0] = t1[0]; b_l[2][1] = t1[1]; b_l[3][0] = t1[2]; b_l[3][1] = t1[3];
#pragma unroll
                for (int mt = 0; mt < 2; mt++)
#pragma unroll
                    for (int j = 0; j < 4; j++) {
                        float* cc = acc[mt][nh * 4 + j];
                        mma_bf16(cc, a_h[mt], b_h[j]);
                        mma_bf16(cc, a_h[mt], b_l[j]);
                    }
            }
        }
        __syncthreads();
    }

    if constexpr (!GATE) {
        int hd = blockIdx.y * 2 + wc;
#pragma unroll
        for (int mt = 0; mt < 2; mt++) {
#pragma unroll
            for (int half = 0; half < 2; half++) {
                int row = row0 + wr * 32 + mt * 16 + r4 + half * 8;
                float ps = 0.f, pd = 0.f;
#pragma unroll
                for (int nt = 0; nt < 8; nt++) {
                    float c0 = acc[mt][nt][half * 2 + 0];
                    float c1 = acc[mt][nt][half * 2 + 1];
                    int gc = nbase + wc * 64 + nt * 8 + k2;
                    if (row < M)
                        *(uint32_t*)(Cb + (size_t)row * NTT + gc) = packbf(c0, c1);
                    ps += c0 * asrc[gc] + c1 * asrc[gc + 1];
                    pd += c0 * adst[gc] + c1 * adst[gc + 1];
                }
                ps += __shfl_xor_sync(0xffffffffu, ps, 1);
                ps += __shfl_xor_sync(0xffffffffu, ps, 2);
                pd += __shfl_xor_sync(0xffffffffu, pd, 1);
                pd += __shfl_xor_sync(0xffffffffu, pd, 2);
                if (row < M && (lane & 3) == 0) {
                    als[row * 4 + hd] = ps;
                    ald[row * 4 + hd] = pd;
                }
            }
        }
    } else {
        if (tid < 128) sgate[tid] = 0.f;
        __syncthreads();
#pragma unroll
        for (int mt = 0; mt < 2; mt++) {
#pragma unroll
            for (int half = 0; half < 2; half++) {
                int rl = wr * 32 + mt * 16 + r4 + half * 8;
                float p = 0.f;
#pragma unroll
                for (int nt = 0; nt < 8; nt++) {
                    float c0 = acc[mt][nt][half * 2 + 0];
                    float c1 = acc[mt][nt][half * 2 + 1];
                    int gc = wc * 64 + nt * 8 + k2;
                    p += fmaxf(c0 + pb1[gc], 0.f) * pW2[gc];
                    p += fmaxf(c1 + pb1[gc + 1], 0.f) * pW2[gc + 1];
                }
                p += __shfl_xor_sync(0xffffffffu, p, 1);
                p += __shfl_xor_sync(0xffffffffu, p, 2);
                if ((lane & 3) == 0) atomicAdd(&sgate[rl], p);
            }
        }
        __syncthreads();
        if (tid < 128) {
            int row = row0 + tid;
            if (row < M) gate[row] = sgate[tid] + pb2[0];
        }
    }
}

// ---------------- fused edge softmax + aggregate + bias + LN + ReLU ------------
__device__ __forceinline__ float lrelu(float x) { return x > 0.f ? x : 0.2f * x; }

__global__ void edge_agg_k(const int* __restrict__ off, const int* __restrict__ csr,
                           const __nv_bfloat16* __restrict__ hb, const float* __restrict__ als,
                           const float* __restrict__ ald, const float* __restrict__ bias,
                           const float* __restrict__ gamma, const float* __restrict__ beta,
                           __nv_bfloat16* __restrict__ ohi, int n) {
    int node = (blockIdx.x * blockDim.x + threadIdx.x) >> 5;
    int lane = threadIdx.x & 31;
    if (node >= n) return;
    int beg = off[node], end = off[node + 1];

    int hd = lane >> 3;
    int eoff = lane & 7;
    float adh = ald[node * 4 + hd];

    float sexp = 0.f;
    float4 a0 = make_float4(0.f, 0.f, 0.f, 0.f);
    float4 a1 = make_float4(0.f, 0.f, 0.f, 0.f);
    for (int cb = beg; cb < end; cb += 8) {
        int cnt = min(8, end - cb);
        float ev = 0.f;
        int smine = 0;
        if (eoff < cnt) {
            smine = csr[cb + eoff];
            ev = __expf(lrelu(als[(size_t)smine * 4 + hd] + adh));
        }
        sexp += ev;
        int lbase = lane & 24;
        for (int e = 0; e < cnt; e++) {
            float w = __shfl_sync(0xffffffffu, ev, lbase + e);
            int se = __shfl_sync(0xffffffffu, smine, e);
            uint4 u = *(const uint4*)(hb + (size_t)se * 256 + lane * 8);
            float2 f0 = __bfloat1622float2(*(__nv_bfloat162*)&u.x);
            float2 f1 = __bfloat1622float2(*(__nv_bfloat162*)&u.y);
            float2 f2 = __bfloat1622float2(*(__nv_bfloat162*)&u.z);
            float2 f3 = __bfloat1622float2(*(__nv_bfloat162*)&u.w);
            a0.x += w * f0.x; a0.y += w * f0.y; a0.z += w * f1.x; a0.w += w * f1.y;
            a1.x += w * f2.x; a1.y += w * f2.y; a1.z += w * f3.x; a1.w += w * f3.y;
        }
    }
    sexp += __shfl_xor_sync(0xffffffffu, sexp, 1);
    sexp += __shfl_xor_sync(0xffffffffu, sexp, 2);
    sexp += __shfl_xor_sync(0xffffffffu, sexp, 4);
    float inv = 1.f / (sexp + 1e-16f);

    const float4* bp = (const float4*)(bias + lane * 8);
    float4 b0 = bp[0], b1 = bp[1];
    float y[8] = { a0.x * inv + b0.x, a0.y * inv + b0.y, a0.z * inv + b0.z, a0.w * inv + b0.w,
                   a1.x * inv + b1.x, a1.y * inv + b1.y, a1.z * inv + b1.z, a1.w * inv + b1.w };
    float ls = 0.f, lq = 0.f;
#pragma unroll
    for (int i = 0; i < 8; i++) { ls += y[i]; lq += y[i] * y[i]; }
#pragma unroll
    for (int o = 16; o > 0; o >>= 1) {
        ls += __shfl_xor_sync(0xffffffffu, ls, o);
        lq += __shfl_xor_sync(0xffffffffu, lq, o);
    }
    float mu  = ls * (1.f / 256.f);
    float var = lq * (1.f / 256.f) - mu * mu;
    float rs  = rsqrtf(var + 1e-5f);
    const float4* gp = (const float4*)(gamma + lane * 8);
    const float4* ep = (const float4*)(beta + lane * 8);
    float4 g0 = gp[0], g1 = gp[1], e0 = ep[0], e1 = ep[1];
    float o8[8];
    o8[0] = fmaxf((y[0] - mu) * rs * g0.x + e0.x, 0.f);
    o8[1] = fmaxf((y[1] - mu) * rs * g0.y + e0.y, 0.f);
    o8[2] = fmaxf((y[2] - mu) * rs * g0.z + e0.z, 0.f);
    o8[3] = fmaxf((y[3] - mu) * rs * g0.w + e0.w, 0.f);
    o8[4] = fmaxf((y[4] - mu) * rs * g1.x + e1.x, 0.f);
    o8[5] = fmaxf((y[5] - mu) * rs * g1.y + e1.y, 0.f);
    o8[6] = fmaxf((y[6] - mu) * rs * g1.z + e1.z, 0.f);
    o8[7] = fmaxf((y[7] - mu) * rs * g1.w + e1.w, 0.f);

    uint4 uh;
    uh.x = packbf(o8[0], o8[1]); uh.y = packbf(o8[2], o8[3]);
    uh.z = packbf(o8[4], o8[5]); uh.w = packbf(o8[6], o8[7]);
    ((uint4*)ohi)[(size_t)node * 32 + lane] = uh;
}

// ---------------- pooling: stats -> parallel accumulate -> classifier ----------
__global__ void pool_stats_k(const float* __restrict__ gate, const int* __restrict__ gstart,
                             float* __restrict__ gm, float* __restrict__ ginv,
                             float* __restrict__ pool) {
    int g = blockIdx.x;
    int t = threadIdx.x;
    int gs = gstart[g], ge = gstart[g + 1];
    __shared__ float red[256];
    float lm = -1e30f;
    for (int nn = gs + t; nn < ge; nn += 256) lm = fmaxf(lm, gate[nn]);
    red[t] = lm; __syncthreads();
    for (int s2 = 128; s2 > 0; s2 >>= 1) {
        if (t < s2) red[t] = fmaxf(red[t], red[t + s2]);
        __syncthreads();
    }
    float m = red[0]; __syncthreads();
    float lsum = 0.f;
    for (int nn = gs + t; nn < ge; nn += 256) lsum += __expf(gate[nn] - m);
    red[t] = lsum; __syncthreads();
    for (int s2 = 128; s2 > 0; s2 >>= 1) {
        if (t < s2) red[t] += red[t + s2];
        __syncthreads();
    }
    if (t == 0) { gm[g] = m; ginv[g] = 1.f / (red[0] + 1e-16f); }
    pool[g * 256 + t] = 0.f;
}

__global__ void pool_acc_k(const __nv_bfloat16* __restrict__ ahi,
                           const float* __restrict__ gate, const int* __restrict__ gstart,
                           const float* __restrict__ gm, const float* __restrict__ ginv,
                           float* __restrict__ pool) {
    int g = blockIdx.x;
    int part = blockIdx.y;
    int t = threadIdx.x;
    int gs = gstart[g], ge = gstart[g + 1];
    int len = ge - gs;
    int chunk = (len + 7) >> 3;
    int ns = gs + part * chunk;
    int ne = min(ns + chunk, ge);
    if (ns >= ne) return;
    float m = gm[g], inv = ginv[g];
    __shared__ float swt[256];
    float acc = 0.f;
    for (int cb = ns; cb < ne; cb += 256) {
        int nn = cb + t;
        swt[t] = (nn < ne) ? __expf(gate[nn] - m) * inv : 0.f;
        __syncthreads();
        int l2 = min(256, ne - cb);
        for (int i = 0; i < l2; i++) {
            size_t idx = (size_t)(cb + i) * 256 + t;
            acc += __bfloat162float(ahi[idx]) * swt[i];
        }
        __syncthreads();
    }
    atomicAdd(&pool[g * 256 + t], acc);
}

__global__ void pool_fin_k(const float* __restrict__ pool, const float* __restrict__ cW1,
                           const float* __restrict__ cb1, const float* __restrict__ cW2,
                           const float* __restrict__ cb2, float* __restrict__ out) {
    int g = blockIdx.x;
    int t = threadIdx.x;
    __shared__ float pooled[256];
    __shared__ float tt[128];
    pooled[t] = pool[g * 256 + t];
    pooled[t + 128] = pool[g * 256 + t + 128];
    __syncthreads();
    float s1 = cb1[t];
#pragma unroll 4
    for (int c = 0; c < 256; c++) s1 += pooled[c] * cW1[c * 128 + t];
    tt[t] = fmaxf(s1, 0.f);
    __syncthreads();
    if (t < 2) {
        float o = cb2[t];
        for (int j = 0; j < 128; j++) o += tt[j] * cW2[j * 2 + t];
        out[g * 2 + t] = o;
    }
}

// ---------------- launch ----------------
extern "C" void kernel_launch(void* const* d_in, const int* in_sizes, int n_in,
                              void* d_out, int out_size) {
    const float* x    = (const float*)d_in[0];
    const int*   ei   = (const int*)  d_in[1];
    const int*   batch= (const int*)  d_in[2];
    const float* W0   = (const float*)d_in[3];
    const float* as0  = (const float*)d_in[4];
    const float* ad0  = (const float*)d_in[5];
    const float* b0   = (const float*)d_in[6];
    const float* gm0  = (const float*)d_in[7];
    const float* be0  = (const float*)d_in[8];
    const float* W1   = (const float*)d_in[9];
    const float* as1  = (const float*)d_in[10];
    const float* ad1  = (const float*)d_in[11];
    const float* b1   = (const float*)d_in[12];
    const float* gm1  = (const float*)d_in[13];
    const float* be1  = (const float*)d_in[14];
    const float* pW1  = (const float*)d_in[15];
    const float* pb1  = (const float*)d_in[16];
    const float* pW2  = (const float*)d_in[17];
    const float* pb2  = (const float*)d_in[18];
    const float* cW1  = (const float*)d_in[19];
    const float* cb1  = (const float*)d_in[20];
    const float* cW2  = (const float*)d_in[21];
    const float* cb2  = (const float*)d_in[22];
    float* out = (float*)d_out;

    int N = in_sizes[0] / 128;
    int E = in_sizes[1] / 2;

    float *als, *ald, *gate, *pool, *gmv, *ginv;
    __nv_bfloat16 *hbb, *ahi, *wt0h, *wt0l, *wt1h, *wt1l, *wtph, *wtpl;
    int *cnt, *off, *fill, *srcv, *gstart, *bsum;
    cudaGetSymbolAddress((void**)&hbb,   g_hb);
    cudaGetSymbolAddress((void**)&ahi,   g_ahi);
    cudaGetSymbolAddress((void**)&wt0h,  g_wt0hi);
    cudaGetSymbolAddress((void**)&wt0l,  g_wt0lo);
    cudaGetSymbolAddress((void**)&wt1h,  g_wt1hi);
    cudaGetSymbolAddress((void**)&wt1l,  g_wt1lo);
    cudaGetSymbolAddress((void**)&wtph,  g_wtphi);
    cudaGetSymbolAddress((void**)&wtpl,  g_wtplo);
    cudaGetSymbolAddress((void**)&als,   g_als);
    cudaGetSymbolAddress((void**)&ald,   g_ald);
    cudaGetSymbolAddress((void**)&gate,  g_gate);
    cudaGetSymbolAddress((void**)&pool,  g_pool);
    cudaGetSymbolAddress((void**)&gmv,   g_gm);
    cudaGetSymbolAddress((void**)&ginv,  g_ginv);
    cudaGetSymbolAddress((void**)&cnt,   g_cnt);
    cudaGetSymbolAddress((void**)&off,   g_off);
    cudaGetSymbolAddress((void**)&fill,  g_fill);
    cudaGetSymbolAddress((void**)&srcv,  g_srcv);
    cudaGetSymbolAddress((void**)&gstart,g_gstart);
    cudaGetSymbolAddress((void**)&bsum,  g_bsum);

    static cudaStream_t s2 = nullptr;
    static cudaEvent_t evFork = nullptr, evJoin = nullptr;
    static bool attr_done = false;
    if (!attr_done) {
        cudaFuncSetAttribute(gemm_mma_k<false>,
                             cudaFuncAttributeMaxDynamicSharedMemorySize, 2 * GSTG);
        cudaFuncSetAttribute(gemm_mma_k<true>,
                             cudaFuncAttributeMaxDynamicSharedMemorySize, 2 * GSTG);
        cudaStreamCreateWithFlags(&s2, cudaStreamNonBlocking);
        cudaEventCreateWithFlags(&evFork, cudaEventDisableTiming);
        cudaEventCreateWithFlags(&evJoin, cudaEventDisableTiming);
        attr_done = true;
    }

    int nb   = (N + 255) / 256;
    int ebk  = (E + 255) / 256;
    int wnb  = (N + 7) / 8;
    int nb1k = (N + 1023) / 1024;
    int gmx  = (N + 127) / 128;
    int npx  = (N * 128 + 255) / 256;

    cudaMemsetAsync(cnt, 0, N * sizeof(int));
    prep_k<<<npx, 256>>>(x, ahi, N * 128, ei, E, cnt,
                         W0, wt0h, wt0l, W1, wt1h, wt1l, pW1, wtph, wtpl);

    // fork: CSR build on s2 concurrent with GEMM-0 on main stream
    cudaEventRecord(evFork, 0);
    cudaStreamWaitEvent(s2, evFork, 0);
    scan_block_k<<<nb1k, 1024, 0, s2>>>(cnt, off, bsum, N, batch, gstart, GI);
    scan_add_fill_k<<<nb, 256, 0, s2>>>(bsum, off, fill, srcv, N, nb1k);
    scatter_k<<<ebk, 256, 0, s2>>>(ei, E, fill, srcv);
    cudaEventRecord(evJoin, s2);

    gemm_mma_k<false><<<dim3(gmx, 2), 256, 2 * GSTG>>>(ahi, wt0h, wt0l, hbb, als, ald,
                                                       as0, ad0, nullptr, nullptr, nullptr,
                                                       nullptr, N, 128, 256);
    cudaStreamWaitEvent(0, evJoin, 0);   // join before edge_agg

    edge_agg_k<<<wnb, 256>>>(off, srcv, hbb, als, ald, b0, gm0, be0, ahi, N);
    gemm_mma_k<false><<<dim3(gmx, 2), 256, 2 * GSTG>>>(ahi, wt1h, wt1l, hbb, als, ald,
                                                       as1, ad1, nullptr, nullptr, nullptr,
                                                       nullptr, N, 256, 256);
    edge_agg_k<<<wnb, 256>>>(off, srcv, hbb, als, ald, b1, gm1, be1, ahi, N);
    gemm_mma_k<true><<<dim3(gmx, 1), 256, 2 * GSTG>>>(ahi, wtph, wtpl, nullptr, nullptr,
                                                      nullptr, nullptr, nullptr, pb1, pW2,
                                                      pb2, gate, N, 256, 128);
    pool_stats_k<<<GI, 256>>>(gate, gstart, gmv, ginv, pool);
    pool_acc_k<<<dim3(GI, 8), 256>>>(ahi, gate, gstart, gmv, ginv, pool);
    pool_fin_k<<<GI, 128>>>(pool, cW1, cb1, cW2, cb2, out);
}

// round 17
// speedup vs baseline: 1.1847x; 1.0050x over previous
#include <cuda_runtime.h>
#include <cuda_bf16.h>
#include <math.h>
#include <stdint.h>

#define NN 50000
#define EE 800000
#define GI 64
#define HCDIM 256

// ---------------- scratch (static device globals; no allocation) ----------------
__device__ __nv_bfloat16 g_hb[(size_t)NN * HCDIM];   // GEMM output h (bf16, gathered)
__device__ __nv_bfloat16 g_ahi[(size_t)NN * HCDIM];  // A operand (bf16)
__device__ __nv_bfloat16 g_wt0hi[256 * 128], g_wt0lo[256 * 128];
__device__ __nv_bfloat16 g_wt1hi[256 * 256], g_wt1lo[256 * 256];
__device__ __nv_bfloat16 g_wtphi[128 * 256];
__device__ float g_als[NN * 4];
__device__ float g_ald[NN * 4];
__device__ float g_gate[NN];
__device__ float g_pool[GI * HCDIM];
__device__ float g_gm[GI];
__device__ float g_ginv[GI];
__device__ int   g_cnt[NN];
__device__ int   g_off[NN + 1];
__device__ int   g_fill[NN];
__device__ int   g_srcv[EE + NN];
__device__ int   g_gstart[GI + 1];
__device__ int   g_bsum[64];

// ---------------- helpers ----------------
__device__ __forceinline__ void mma_bf16(float* c, const uint32_t* a, const uint32_t* b) {
    asm volatile(
        "mma.sync.aligned.m16n8k16.row.col.f32.bf16.bf16.f32 "
        "{%0,%1,%2,%3}, {%4,%5,%6,%7}, {%8,%9}, {%0,%1,%2,%3};"
        : "+f"(c[0]), "+f"(c[1]), "+f"(c[2]), "+f"(c[3])
        : "r"(a[0]), "r"(a[1]), "r"(a[2]), "r"(a[3]), "r"(b[0]), "r"(b[1]));
}
#define LDM4(r, addr) \
    asm volatile("ldmatrix.sync.aligned.m8n8.x4.shared.b16 {%0,%1,%2,%3}, [%4];" \
        : "=r"((r)[0]), "=r"((r)[1]), "=r"((r)[2]), "=r"((r)[3]) : "r"(addr))
__device__ __forceinline__ uint32_t smem_u32(const void* p) {
    uint32_t a;
    asm("{ .reg .u64 t; cvta.to.shared.u64 t, %1; cvt.u32.u64 %0, t; }" : "=r"(a) : "l"(p));
    return a;
}
__device__ __forceinline__ void cpa16(uint32_t dst, const void* src, uint32_t sz) {
    asm volatile("cp.async.cg.shared.global [%0], [%1], 16, %2;"
                 :: "r"(dst), "l"(src), "r"(sz));
}
#define CP_COMMIT() asm volatile("cp.async.commit_group;")
#define CP_WAIT(n)  asm volatile("cp.async.wait_group %0;" :: "n"(n))
__device__ __forceinline__ uint32_t packbf(float a, float b) {
    return (uint32_t)__bfloat16_as_ushort(__float2bfloat16(a)) |
           ((uint32_t)__bfloat16_as_ushort(__float2bfloat16(b)) << 16);
}

// ---------------- prep split: edge-count (s2) / everything else (main) ----------
__global__ void prep_cnt_k(const int* __restrict__ ei, int E, int* cnt) {
    int i = blockIdx.x * blockDim.x + threadIdx.x;
    if (i < E) atomicAdd(&cnt[ei[E + i]], 1);
}
__global__ void prep_rest_k(const float* __restrict__ x, __nv_bfloat16* xhi, int nx,
                            const float* __restrict__ W0, __nv_bfloat16* w0h, __nv_bfloat16* w0l,
                            const float* __restrict__ W1, __nv_bfloat16* w1h, __nv_bfloat16* w1l,
                            const float* __restrict__ pW1, __nv_bfloat16* wph) {
    int i = blockIdx.x * blockDim.x + threadIdx.x;
    if (i < nx) xhi[i] = __float2bfloat16(x[i]);
    if (i < 128 * 256) {
        int k = i >> 8, n = i & 255;
        float v = W0[i];
        __nv_bfloat16 h = __float2bfloat16(v);
        w0h[n * 128 + k] = h;
        w0l[n * 128 + k] = __float2bfloat16(v - __bfloat162float(h));
    }
    if (i < 256 * 256) {
        int k = i >> 8, n = i & 255;
        float v = W1[i];
        __nv_bfloat16 h = __float2bfloat16(v);
        w1h[n * 256 + k] = h;
        w1l[n * 256 + k] = __float2bfloat16(v - __bfloat162float(h));
    }
    if (i < 256 * 128) {
        int k = i >> 7, n = i & 127;
        wph[n * 256 + k] = __float2bfloat16(pW1[i]);
    }
}

// ---------------- CSR scan (+fused gstart) ----------------
__global__ void scan_block_k(const int* __restrict__ cnt, int* __restrict__ off,
                             int* __restrict__ bsum, int n,
                             const int* __restrict__ batch, int* __restrict__ gstart, int G) {
    int i = blockIdx.x * 1024 + threadIdx.x;
    int lane = threadIdx.x & 31, wid = threadIdx.x >> 5;
    int v = (i < n) ? cnt[i] + 1 : 0;   // +1 = self loop
    int s = v;
#pragma unroll
    for (int d = 1; d < 32; d <<= 1) {
        int t = __shfl_up_sync(0xffffffffu, s, d);
        if (lane >= d) s += t;
    }
    __shared__ int wsum[32];
    if (lane == 31) wsum[wid] = s;
    __syncthreads();
    if (wid == 0) {
        int w = wsum[lane];
#pragma unroll
        for (int d = 1; d < 32; d <<= 1) {
            int t = __shfl_up_sync(0xffffffffu, w, d);
            if (lane >= d) w += t;
        }
        wsum[lane] = w;
    }
    __syncthreads();
    int base = wid ? wsum[wid - 1] : 0;
    if (i < n) off[i] = base + s - v;
    if (threadIdx.x == 1023) bsum[blockIdx.x] = base + s;
    if (i < n) {
        int b = batch[i];
        if (i == 0) { for (int g = 0; g <= b; g++) gstart[g] = 0; }
        else {
            int pb = batch[i - 1];
            if (pb != b) for (int g = pb + 1; g <= b; g++) gstart[g] = i;
        }
        if (i == n - 1) for (int g = b + 1; g <= G; g++) gstart[g] = n;
    }
}
__global__ void scan_add_fill_k(const int* __restrict__ bsum, int* __restrict__ off,
                                int* __restrict__ fill, int* __restrict__ srcv,
                                int n, int nb) {
    __shared__ int sh[64];
    int t = threadIdx.x;   // 256
    if (t < 64) sh[t] = (t < nb) ? bsum[t] : 0;
    __syncthreads();
#pragma unroll
    for (int d = 1; d < 64; d <<= 1) {
        int x = (t >= d && t < 64) ? sh[t - d] : 0;
        __syncthreads();
        if (t < 64) sh[t] += x;
        __syncthreads();
    }
    int i = blockIdx.x * 256 + t;
    if (i < n) {
        int b = i >> 10;
        int o = off[i] + (b ? sh[b - 1] : 0);
        off[i] = o;
        fill[i] = o + 1;
        srcv[o] = i;
    }
    if (blockIdx.x == 0 && t == 0) off[n] = sh[nb - 1];
}
__global__ void scatter_k(const int* __restrict__ ei, int E, int* fill, int* srcv) {
    int e = blockIdx.x * blockDim.x + threadIdx.x;
    if (e < E) {
        int s = ei[e];
        int d = ei[E + e];
        int p = atomicAdd(&fill[d], 1);
        srcv[p] = s;
    }
}

// ---------------- HMMA GEMM, 3-stage cp.async pipeline --------------------------
// GATE=false: D = A·Bh + A·Bl (weight hi/lo). GATE=true: D = A·Bh only.
#define GSTG 30720
#define OFF_AH 0
#define OFF_BH 10240
#define OFF_BL 20480
template <bool GATE>
__global__ __launch_bounds__(256, 2)
void gemm_mma_k(const __nv_bfloat16* __restrict__ ahi,
                const __nv_bfloat16* __restrict__ bhi, const __nv_bfloat16* __restrict__ blo,
                __nv_bfloat16* __restrict__ Cb, float* __restrict__ als, float* __restrict__ ald,
                const float* __restrict__ asrc, const float* __restrict__ adst,
                const float* __restrict__ pb1, const float* __restrict__ pW2,
                const float* __restrict__ pb2, float* __restrict__ gate,
                int M, int K, int NTT) {
    extern __shared__ char dynsm[];
    __shared__ float sgate[128];
    uint32_t sbase = smem_u32(dynsm);

    int tid = threadIdx.x;
    int wid = tid >> 5, lane = tid & 31;
    int wr = wid >> 1, wc = wid & 1;
    int row0 = blockIdx.x * 128;
    int nbase = blockIdx.y * 128;

    float acc[2][8][4];
#pragma unroll
    for (int mt = 0; mt < 2; mt++)
#pragma unroll
        for (int nt = 0; nt < 8; nt++)
#pragma unroll
            for (int q = 0; q < 4; q++) acc[mt][nt][q] = 0.f;

    int r4 = lane >> 2, k2 = (lane & 3) * 2;
    uint32_t aoffB = (uint32_t)(((wr * 32 + (lane & 15)) * 40 + (lane >> 4) * 8) * 2);
    uint32_t boffB = (uint32_t)(((wc * 64 + ((lane >> 4) & 1) * 8 + (lane & 7)) * 40 +
                                 ((lane >> 3) & 1) * 8) * 2);

    int ntiles = K >> 5;
    auto issue = [&](int kt) {
        uint32_t sb2 = sbase + (uint32_t)(kt % 3) * GSTG;
        int kbase = kt << 5;
#pragma unroll
        for (int i = 0; i < 2; i++) {
            int idx = tid + i * 256;
            int r = idx >> 2, q = idx & 3;
            int row = row0 + r;
            uint32_t doff = (uint32_t)((r * 40 + q * 8) * 2);
            size_t ga = (size_t)row * K + kbase + q * 8;
            uint32_t sz = (row < M) ? 16u : 0u;
            cpa16(sb2 + OFF_AH + doff, ahi + ga, sz);
            size_t gb = (size_t)(nbase + r) * K + kbase + q * 8;
            cpa16(sb2 + OFF_BH + doff, bhi + gb, 16u);
            if constexpr (!GATE) cpa16(sb2 + OFF_BL + doff, blo + gb, 16u);
        }
        CP_COMMIT();
    };

    issue(0);
    if (ntiles > 1) issue(1);
    for (int kt = 0; kt < ntiles; kt++) {
        if (kt + 2 < ntiles) { issue(kt + 2); CP_WAIT(2); }
        else if (kt + 1 < ntiles) { CP_WAIT(1); }
        else { CP_WAIT(0); }
        __syncthreads();
        uint32_t sb2 = sbase + (uint32_t)(kt % 3) * GSTG;
#pragma unroll
        for (int kk = 0; kk < 32; kk += 16) {
            uint32_t a_h[2][4];
            uint32_t ab = aoffB + kk * 2;
            LDM4(a_h[0], sb2 + OFF_AH + ab);
            LDM4(a_h[1], sb2 + OFF_AH + ab + 16 * 80);
#pragma unroll
            for (int nh = 0; nh < 2; nh++) {
                uint32_t b_h[4][2], b_l[4][2];
                uint32_t bb = boffB + (nh * 32 * 40 + kk) * 2;
                uint32_t t0[4], t1[4];
                LDM4(t0, sb2 + OFF_BH + bb);
                LDM4(t1, sb2 + OFF_BH + bb + 16 * 80);
                b_h[0][0] = t0[0]; b_h[0][1] = t0[1]; b_h[1][0] = t0[2]; b_h[1][1] = t0[3];
                b_h[2][0] = t1[0]; b_h[2][1] = t1[1]; b_h[3][0] = t1[2]; b_h[3][1] = t1[3];
                if constexpr (!GATE) {
                    LDM4(t0, sb2 + OFF_BL + bb);
                    LDM4(t1, sb2 + OFF_BL + bb + 16 * 80);
                    b_l[0][0] = t0[0]; b_l[0][1] = t0[1]; b_l[1][0] = t0[2]; b_l[1][1] = t0[3];
                    b_l[2][0] = t1[0]; b_l[2][1] = t1[1]; b_l[3][0] = t1[2]; b_l[3][1] = t1[3];
                }
#pragma unroll
                for (int mt = 0; mt < 2; mt++)
#pragma unroll
                    for (int j = 0; j < 4; j++) {
                        float* cc = acc[mt][nh * 4 + j];
                        mma_bf16(cc, a_h[mt], b_h[j]);
                        if constexpr (!GATE) mma_bf16(cc, a_h[mt], b_l[j]);
                    }
            }
        }
        __syncthreads();
    }

    if constexpr (!GATE) {
        int hd = blockIdx.y * 2 + wc;
#pragma unroll
        for (int mt = 0; mt < 2; mt++) {
#pragma unroll
            for (int half = 0; half < 2; half++) {
                int row = row0 + wr * 32 + mt * 16 + r4 + half * 8;
                float ps = 0.f, pd = 0.f;
#pragma unroll
                for (int nt = 0; nt < 8; nt++) {
                    float c0 = acc[mt][nt][half * 2 + 0];
                    float c1 = acc[mt][nt][half * 2 + 1];
                    int gc = nbase + wc * 64 + nt * 8 + k2;
                    if (row < M)
                        *(uint32_t*)(Cb + (size_t)row * NTT + gc) = packbf(c0, c1);
                    ps += c0 * asrc[gc] + c1 * asrc[gc + 1];
                    pd += c0 * adst[gc] + c1 * adst[gc + 1];
                }
                ps += __shfl_xor_sync(0xffffffffu, ps, 1);
                ps += __shfl_xor_sync(0xffffffffu, ps, 2);
                pd += __shfl_xor_sync(0xffffffffu, pd, 1);
                pd += __shfl_xor_sync(0xffffffffu, pd, 2);
                if (row < M && (lane & 3) == 0) {
                    als[row * 4 + hd] = ps;
                    ald[row * 4 + hd] = pd;
                }
            }
        }
    } else {
        if (tid < 128) sgate[tid] = 0.f;
        __syncthreads();
#pragma unroll
        for (int mt = 0; mt < 2; mt++) {
#pragma unroll
            for (int half = 0; half < 2; half++) {
                int rl = wr * 32 + mt * 16 + r4 + half * 8;
                float p = 0.f;
#pragma unroll
                for (int nt = 0; nt < 8; nt++) {
                    float c0 = acc[mt][nt][half * 2 + 0];
                    float c1 = acc[mt][nt][half * 2 + 1];
                    int gc = wc * 64 + nt * 8 + k2;
                    p += fmaxf(c0 + pb1[gc], 0.f) * pW2[gc];
                    p += fmaxf(c1 + pb1[gc + 1], 0.f) * pW2[gc + 1];
                }
                p += __shfl_xor_sync(0xffffffffu, p, 1);
                p += __shfl_xor_sync(0xffffffffu, p, 2);
                if ((lane & 3) == 0) atomicAdd(&sgate[rl], p);
            }
        }
        __syncthreads();
        if (tid < 128) {
            int row = row0 + tid;
            if (row < M) gate[row] = sgate[tid] + pb2[0];
        }
    }
}

// ---------------- fused edge softmax + aggregate + bias + LN + ReLU ------------
__device__ __forceinline__ float lrelu(float x) { return x > 0.f ? x : 0.2f * x; }

__global__ void edge_agg_k(const int* __restrict__ off, const int* __restrict__ csr,
                           const __nv_bfloat16* __restrict__ hb, const float* __restrict__ als,
                           const float* __restrict__ ald, const float* __restrict__ bias,
                           const float* __restrict__ gamma, const float* __restrict__ beta,
                           __nv_bfloat16* __restrict__ ohi, int n) {
    int node = (blockIdx.x * blockDim.x + threadIdx.x) >> 5;
    int lane = threadIdx.x & 31;
    if (node >= n) return;
    int beg = off[node], end = off[node + 1];

    int hd = lane >> 3;
    int eoff = lane & 7;
    float adh = ald[node * 4 + hd];

    float sexp = 0.f;
    float4 a0 = make_float4(0.f, 0.f, 0.f, 0.f);
    float4 a1 = make_float4(0.f, 0.f, 0.f, 0.f);
    for (int cb = beg; cb < end; cb += 8) {
        int cnt = min(8, end - cb);
        float ev = 0.f;
        int smine = 0;
        if (eoff < cnt) {
            smine = csr[cb + eoff];
            ev = __expf(lrelu(als[(size_t)smine * 4 + hd] + adh));
        }
        sexp += ev;
        int lbase = lane & 24;
        for (int e = 0; e < cnt; e++) {
            float w = __shfl_sync(0xffffffffu, ev, lbase + e);
            int se = __shfl_sync(0xffffffffu, smine, e);
            uint4 u = *(const uint4*)(hb + (size_t)se * 256 + lane * 8);
            float2 f0 = __bfloat1622float2(*(__nv_bfloat162*)&u.x);
            float2 f1 = __bfloat1622float2(*(__nv_bfloat162*)&u.y);
            float2 f2 = __bfloat1622float2(*(__nv_bfloat162*)&u.z);
            float2 f3 = __bfloat1622float2(*(__nv_bfloat162*)&u.w);
            a0.x += w * f0.x; a0.y += w * f0.y; a0.z += w * f1.x; a0.w += w * f1.y;
            a1.x += w * f2.x; a1.y += w * f2.y; a1.z += w * f3.x; a1.w += w * f3.y;
        }
    }
    sexp += __shfl_xor_sync(0xffffffffu, sexp, 1);
    sexp += __shfl_xor_sync(0xffffffffu, sexp, 2);
    sexp += __shfl_xor_sync(0xffffffffu, sexp, 4);
    float inv = 1.f / (sexp + 1e-16f);

    const float4* bp = (const float4*)(bias + lane * 8);
    float4 b0 = bp[0], b1 = bp[1];
    float y[8] = { a0.x * inv + b0.x, a0.y * inv + b0.y, a0.z * inv + b0.z, a0.w * inv + b0.w,
                   a1.x * inv + b1.x, a1.y * inv + b1.y, a1.z * inv + b1.z, a1.w * inv + b1.w };
    float ls = 0.f, lq = 0.f;
#pragma unroll
    for (int i = 0; i < 8; i++) { ls += y[i]; lq += y[i] * y[i]; }
#pragma unroll
    for (int o = 16; o > 0; o >>= 1) {
        ls += __shfl_xor_sync(0xffffffffu, ls, o);
        lq += __shfl_xor_sync(0xffffffffu, lq, o);
    }
    float mu  = ls * (1.f / 256.f);
    float var = lq * (1.f / 256.f) - mu * mu;
    float rs  = rsqrtf(var + 1e-5f);
    const float4* gp = (const float4*)(gamma + lane * 8);
    const float4* ep = (const float4*)(beta + lane * 8);
    float4 g0 = gp[0], g1 = gp[1], e0 = ep[0], e1 = ep[1];
    float o8[8];
    o8[0] = fmaxf((y[0] - mu) * rs * g0.x + e0.x, 0.f);
    o8[1] = fmaxf((y[1] - mu) * rs * g0.y + e0.y, 0.f);
    o8[2] = fmaxf((y[2] - mu) * rs * g0.z + e0.z, 0.f);
    o8[3] = fmaxf((y[3] - mu) * rs * g0.w + e0.w, 0.f);
    o8[4] = fmaxf((y[4] - mu) * rs * g1.x + e1.x, 0.f);
    o8[5] = fmaxf((y[5] - mu) * rs * g1.y + e1.y, 0.f);
    o8[6] = fmaxf((y[6] - mu) * rs * g1.z + e1.z, 0.f);
    o8[7] = fmaxf((y[7] - mu) * rs * g1.w + e1.w, 0.f);

    uint4 uh;
    uh.x = packbf(o8[0], o8[1]); uh.y = packbf(o8[2], o8[3]);
    uh.z = packbf(o8[4], o8[5]); uh.w = packbf(o8[6], o8[7]);
    ((uint4*)ohi)[(size_t)node * 32 + lane] = uh;
}

// ---------------- pooling: stats -> parallel accumulate -> classifier ----------
__global__ void pool_stats_k(const float* __restrict__ gate, const int* __restrict__ gstart,
                             float* __restrict__ gm, float* __restrict__ ginv,
                             float* __restrict__ pool) {
    int g = blockIdx.x;
    int t = threadIdx.x;
    int gs = gstart[g], ge = gstart[g + 1];
    __shared__ float red[256];
    float lm = -1e30f;
    for (int nn = gs + t; nn < ge; nn += 256) lm = fmaxf(lm, gate[nn]);
    red[t] = lm; __syncthreads();
    for (int s2 = 128; s2 > 0; s2 >>= 1) {
        if (t < s2) red[t] = fmaxf(red[t], red[t + s2]);
        __syncthreads();
    }
    float m = red[0]; __syncthreads();
    float lsum = 0.f;
    for (int nn = gs + t; nn < ge; nn += 256) lsum += __expf(gate[nn] - m);
    red[t] = lsum; __syncthreads();
    for (int s2 = 128; s2 > 0; s2 >>= 1) {
        if (t < s2) red[t] += red[t + s2];
        __syncthreads();
    }
    if (t == 0) { gm[g] = m; ginv[g] = 1.f / (red[0] + 1e-16f); }
    pool[g * 256 + t] = 0.f;
}

__global__ void pool_acc_k(const __nv_bfloat16* __restrict__ ahi,
                           const float* __restrict__ gate, const int* __restrict__ gstart,
                           const float* __restrict__ gm, const float* __restrict__ ginv,
                           float* __restrict__ pool) {
    int g = blockIdx.x;
    int part = blockIdx.y;
    int t = threadIdx.x;
    int gs = gstart[g], ge = gstart[g + 1];
    int len = ge - gs;
    int chunk = (len + 7) >> 3;
    int ns = gs + part * chunk;
    int ne = min(ns + chunk, ge);
    if (ns >= ne) return;
    float m = gm[g], inv = ginv[g];
    __shared__ float swt[256];
    float acc = 0.f;
    for (int cb = ns; cb < ne; cb += 256) {
        int nn = cb + t;
        swt[t] = (nn < ne) ? __expf(gate[nn] - m) * inv : 0.f;
        __syncthreads();
        int l2 = min(256, ne - cb);
        for (int i = 0; i < l2; i++) {
            size_t idx = (size_t)(cb + i) * 256 + t;
            acc += __bfloat162float(ahi[idx]) * swt[i];
        }
        __syncthreads();
    }
    atomicAdd(&pool[g * 256 + t], acc);
}

__global__ void pool_fin_k(const float* __restrict__ pool, const float* __restrict__ cW1,
                           const float* __restrict__ cb1, const float* __restrict__ cW2,
                           const float* __restrict__ cb2, float* __restrict__ out) {
    int g = blockIdx.x;
    int t = threadIdx.x;
    __shared__ float pooled[256];
    __shared__ float tt[128];
    pooled[t] = pool[g * 256 + t];
    pooled[t + 128] = pool[g * 256 + t + 128];
    __syncthreads();
    float s1 = cb1[t];
#pragma unroll 4
    for (int c = 0; c < 256; c++) s1 += pooled[c] * cW1[c * 128 + t];
    tt[t] = fmaxf(s1, 0.f);
    __syncthreads();
    if (t < 2) {
        float o = cb2[t];
        for (int j = 0; j < 128; j++) o += tt[j] * cW2[j * 2 + t];
        out[g * 2 + t] = o;
    }
}

// ---------------- launch ----------------
extern "C" void kernel_launch(void* const* d_in, const int* in_sizes, int n_in,
                              void* d_out, int out_size) {
    const float* x    = (const float*)d_in[0];
    const int*   ei   = (const int*)  d_in[1];
    const int*   batch= (const int*)  d_in[2];
    const float* W0   = (const float*)d_in[3];
    const float* as0  = (const float*)d_in[4];
    const float* ad0  = (const float*)d_in[5];
    const float* b0   = (const float*)d_in[6];
    const float* gm0  = (const float*)d_in[7];
    const float* be0  = (const float*)d_in[8];
    const float* W1   = (const float*)d_in[9];
    const float* as1  = (const float*)d_in[10];
    const float* ad1  = (const float*)d_in[11];
    const float* b1   = (const float*)d_in[12];
    const float* gm1  = (const float*)d_in[13];
    const float* be1  = (const float*)d_in[14];
    const float* pW1  = (const float*)d_in[15];
    const float* pb1  = (const float*)d_in[16];
    const float* pW2  = (const float*)d_in[17];
    const float* pb2  = (const float*)d_in[18];
    const float* cW1  = (const float*)d_in[19];
    const float* cb1  = (const float*)d_in[20];
    const float* cW2  = (const float*)d_in[21];
    const float* cb2  = (const float*)d_in[22];
    float* out = (float*)d_out;

    int N = in_sizes[0] / 128;
    int E = in_sizes[1] / 2;

    float *als, *ald, *gate, *pool, *gmv, *ginv;
    __nv_bfloat16 *hbb, *ahi, *wt0h, *wt0l, *wt1h, *wt1l, *wtph;
    int *cnt, *off, *fill, *srcv, *gstart, *bsum;
    cudaGetSymbolAddress((void**)&hbb,   g_hb);
    cudaGetSymbolAddress((void**)&ahi,   g_ahi);
    cudaGetSymbolAddress((void**)&wt0h,  g_wt0hi);
    cudaGetSymbolAddress((void**)&wt0l,  g_wt0lo);
    cudaGetSymbolAddress((void**)&wt1h,  g_wt1hi);
    cudaGetSymbolAddress((void**)&wt1l,  g_wt1lo);
    cudaGetSymbolAddress((void**)&wtph,  g_wtphi);
    cudaGetSymbolAddress((void**)&als,   g_als);
    cudaGetSymbolAddress((void**)&ald,   g_ald);
    cudaGetSymbolAddress((void**)&gate,  g_gate);
    cudaGetSymbolAddress((void**)&pool,  g_pool);
    cudaGetSymbolAddress((void**)&gmv,   g_gm);
    cudaGetSymbolAddress((void**)&ginv,  g_ginv);
    cudaGetSymbolAddress((void**)&cnt,   g_cnt);
    cudaGetSymbolAddress((void**)&off,   g_off);
    cudaGetSymbolAddress((void**)&fill,  g_fill);
    cudaGetSymbolAddress((void**)&srcv,  g_srcv);
    cudaGetSymbolAddress((void**)&gstart,g_gstart);
    cudaGetSymbolAddress((void**)&bsum,  g_bsum);

    static cudaStream_t s2 = nullptr;
    static cudaEvent_t evFork = nullptr, evJoin = nullptr;
    static bool attr_done = false;
    if (!attr_done) {
        cudaFuncSetAttribute(gemm_mma_k<false>,
                             cudaFuncAttributeMaxDynamicSharedMemorySize, 3 * GSTG);
        cudaFuncSetAttribute(gemm_mma_k<true>,
                             cudaFuncAttributeMaxDynamicSharedMemorySize, 3 * GSTG);
        cudaStreamCreateWithFlags(&s2, cudaStreamNonBlocking);
        cudaEventCreateWithFlags(&evFork, cudaEventDisableTiming);
        cudaEventCreateWithFlags(&evJoin, cudaEventDisableTiming);
        attr_done = true;
    }

    int nb   = (N + 255) / 256;
    int ebk  = (E + 255) / 256;
    int wnb  = (N + 7) / 8;
    int nb1k = (N + 1023) / 1024;
    int gmx  = (N + 127) / 128;
    int npx  = (N * 128 + 255) / 256;

    // fork FIRST: full CSR chain (memset -> count -> scan -> fill -> scatter) on s2,
    // concurrent with prep_rest + GEMM-0 on the main stream.
    cudaEventRecord(evFork, 0);
    cudaStreamWaitEvent(s2, evFork, 0);
    cudaMemsetAsync(cnt, 0, N * sizeof(int), s2);
    prep_cnt_k<<<ebk, 256, 0, s2>>>(ei, E, cnt);
    scan_block_k<<<nb1k, 1024, 0, s2>>>(cnt, off, bsum, N, batch, gstart, GI);
    scan_add_fill_k<<<nb, 256, 0, s2>>>(bsum, off, fill, srcv, N, nb1k);
    scatter_k<<<ebk, 256, 0, s2>>>(ei, E, fill, srcv);
    cudaEventRecord(evJoin, s2);

    prep_rest_k<<<npx, 256>>>(x, ahi, N * 128, W0, wt0h, wt0l, W1, wt1h, wt1l, pW1, wtph);
    gemm_mma_k<false><<<dim3(gmx, 2), 256, 3 * GSTG>>>(ahi, wt0h, wt0l, hbb, als, ald,
                                                       as0, ad0, nullptr, nullptr, nullptr,
                                                       nullptr, N, 128, 256);
    cudaStreamWaitEvent(0, evJoin, 0);   // join before edge_agg

    edge_agg_k<<<wnb, 256>>>(off, srcv, hbb, als, ald, b0, gm0, be0, ahi, N);
    gemm_mma_k<false><<<dim3(gmx, 2), 256, 3 * GSTG>>>(ahi, wt1h, wt1l, hbb, als, ald,
                                                       as1, ad1, nullptr, nullptr, nullptr,
                                                       nullptr, N, 256, 256);
    edge_agg_k<<<wnb, 256>>>(off, srcv, hbb, als, ald, b1, gm1, be1, ahi, N);
    gemm_mma_k<true><<<dim3(gmx, 1), 256, 3 * GSTG>>>(ahi, wtph, nullptr, nullptr, nullptr,
                                                      nullptr, nullptr, nullptr, pb1, pW2,
                                                      pb2, gate, N, 256, 128);
    pool_stats_k<<<GI, 256>>>(gate, gstart, gmv, ginv, pool);
    pool_acc_k<<<dim3(GI, 8), 256>>>(ahi, gate, gstart, gmv, ginv, pool);
    pool_fin_k<<<GI, 128>>>(pool, cW1, cb1, cW2, cb2, out);
}